// round 12
// baseline (speedup 1.0000x reference)
#include <cuda_runtime.h>
#include <math.h>
#include <stdint.h>

typedef unsigned long long ull;

#define SS 512
#define NBLK 128

// ---------------- device scratch ----------------
__device__ float g_WTenc[2048 * 4096];   // [k][n'=4j+g]; rows 0..1023 Wih^T, 1024..2047 Whh^T
__device__ float g_WTdec[2048 * 4096];
__device__ float g_WTfc [1024 * 1024];   // [k][n] = fcW[n][k]
__device__ float g_W0   [1024 * 4096];   // (Whh + Wih·fcW)^T packed [j][n']
__device__ float g_gatesX[(size_t)512 * 4096 * 64]; // [t][n'][b]
__device__ float g_tgtX  [(size_t)512 * 4096 * 64]; // [t][n'][b]
__device__ float g_H     [(size_t)512 * 1024 * 64]; // decoder h history [t][j][b]
__device__ float g_hE  [1024 * 64];      // encoder h [j][b]
__device__ float g_dec0[2048 * 64];      // [x_last | h_enc] [k][b]
__device__ float g_c   [1024 * 64];      // [j][b]
__device__ float g_partG[4][4096 * 64];  // gate partials [kz][n'][b]
__device__ float g_bpe[4096], g_bpd[4096], g_bfu[4096];
__device__ int   g_mask[512];
__device__ unsigned           g_barLeaf[16 * 32];
__device__ unsigned           g_barRoot;
__device__ volatile unsigned  g_barGen;

// ---------------- f32x2 helpers ----------------
__device__ __forceinline__ ull dup2(float v) {
    ull r; unsigned u = __float_as_uint(v);
    asm("mov.b64 %0, {%1, %1};" : "=l"(r) : "r"(u));
    return r;
}
__device__ __forceinline__ void fma2(ull& acc, ull a, ull b) {
    asm("fma.rn.f32x2 %0, %1, %2, %0;" : "+l"(acc) : "l"(a), "l"(b));
}
__device__ __forceinline__ float2 unpack2(ull v) {
    unsigned lo, hi;
    asm("mov.b64 {%0, %1}, %2;" : "=r"(lo), "=r"(hi) : "l"(v));
    return make_float2(__uint_as_float(lo), __uint_as_float(hi));
}
__device__ __forceinline__ float sigf(float x) { return 1.0f / (1.0f + expf(-x)); }

// ---------------- grid barrier (128 arrivals: 16 leaves x 8) ----------------
__device__ __forceinline__ void grid_sync(unsigned n) {
    __syncthreads();
    if (threadIdx.x == 0) {
        __threadfence();
        unsigned leaf = (blockIdx.x >> 3) * 32;
        if (atomicAdd(&g_barLeaf[leaf], 1u) + 1u == n * 8u) {
            if (atomicAdd(&g_barRoot, 1u) + 1u == n * 16u) {
                g_barGen = n;
            }
        }
        while (g_barGen < n) { }
        __threadfence();
    }
    __syncthreads();
}

// ============ gate GEMM (512 threads): tile 64b x 128n, double-buffered staging ============
// per-thread: ty=tid>>5 (0..15) -> 4 b (2 pairs), tx=tid&31 -> 4 cols. 8 fma2/kk.
__device__ __forceinline__ void gemm_gate(const float* __restrict__ A,
                                          const float* __restrict__ Wp,
                                          int nKT, float* As, float* Ws,
                                          float* __restrict__ dst, int tid)
{
    const int ty = tid >> 5, tx = tid & 31;
    ull acc[2][4];
#pragma unroll
    for (int q = 0; q < 2; ++q)
#pragma unroll
        for (int c = 0; c < 4; ++c) acc[q][c] = 0ull;

    const int ak = tid >> 4, ab4 = tid & 15;        // A staging: 1 float4/thread
    float4 pa, pw[2];
    pa = *(const float4*)(A + (size_t)ak * 64 + ab4 * 4);
#pragma unroll
    for (int i = 0; i < 2; ++i) {
        int idx = tid + i * 512;
        pw[i] = *(const float4*)(Wp + (size_t)(idx >> 5) * 4096 + (idx & 31) * 4);
    }
    // stage 0
    *(float4*)&As[ak * 64 + ab4 * 4] = pa;
#pragma unroll
    for (int i = 0; i < 2; ++i) {
        int idx = tid + i * 512;
        *(float4*)&Ws[(idx >> 5) * 128 + (idx & 31) * 4] = pw[i];
    }
    __syncthreads();

    for (int kt = 0; kt < nKT; ++kt) {
        const int cb = kt & 1;
        const float* Asc = As + cb * (32 * 64);
        const float* Wsc = Ws + cb * (32 * 128);
        const bool more = (kt + 1 < nKT);
        if (more) {
            int kOff = (kt + 1) * 32;
            pa = *(const float4*)(A + (size_t)(kOff + ak) * 64 + ab4 * 4);
#pragma unroll
            for (int i = 0; i < 2; ++i) {
                int idx = tid + i * 512;
                pw[i] = *(const float4*)(Wp + (size_t)(kOff + (idx >> 5)) * 4096 + (idx & 31) * 4);
            }
        }
#pragma unroll
        for (int kk = 0; kk < 32; ++kk) {
            ulonglong2 aa = *(const ulonglong2*)&Asc[kk * 64 + 4 * ty];    // 2 b-pairs
            float4 wv = *(const float4*)&Wsc[kk * 128 + 4 * tx];
            ull w0 = dup2(wv.x), w1 = dup2(wv.y), w2 = dup2(wv.z), w3 = dup2(wv.w);
            fma2(acc[0][0], aa.x, w0); fma2(acc[0][1], aa.x, w1);
            fma2(acc[0][2], aa.x, w2); fma2(acc[0][3], aa.x, w3);
            fma2(acc[1][0], aa.y, w0); fma2(acc[1][1], aa.y, w1);
            fma2(acc[1][2], aa.y, w2); fma2(acc[1][3], aa.y, w3);
        }
        if (more) {
            float* Asn = As + (cb ^ 1) * (32 * 64);
            float* Wsn = Ws + (cb ^ 1) * (32 * 128);
            *(float4*)&Asn[ak * 64 + ab4 * 4] = pa;
#pragma unroll
            for (int i = 0; i < 2; ++i) {
                int idx = tid + i * 512;
                *(float4*)&Wsn[(idx >> 5) * 128 + (idx & 31) * 4] = pw[i];
            }
        }
        __syncthreads();
    }
    // store partial [col][b]
#pragma unroll
    for (int q = 0; q < 2; ++q)
#pragma unroll
        for (int c = 0; c < 4; ++c) {
            float2 v = unpack2(acc[q][c]);
            *(float2*)&dst[(4 * tx + c) * 64 + 4 * ty + 2 * q] = v;
        }
}

// ============ persistent kernel: 128 CTAs x 512 threads (1/SM, 16 warps) ============
__global__ __launch_bounds__(512, 1)
void seq2seq_persist(const float* __restrict__ x)
{
    __shared__ __align__(16) float As[2 * 32 * 64];
    __shared__ __align__(16) float Ws[2 * 32 * 128];

    const int tid = threadIdx.x;
    const int bid = blockIdx.x;
    const int p   = bid >> 2;     // 32 n-tiles of 128 cols
    const int kz  = bid & 3;      // K quarter
    const int id  = bid * 512 + tid;            // 0..65535, one element/thread
    const int b   = id & 63;
    const int j   = id >> 6;
    const int np  = 4 * j;
    unsigned ns = 0;

    // ---------------- encoder: h @ Whh^T (K=1024) + gatesX ----------------
    for (int t = 0; t < SS; ++t) {
        gemm_gate(g_hE + (size_t)(kz * 256) * 64,
                  g_WTenc + (size_t)(1024 + kz * 256) * 4096 + p * 128,
                  8, As, Ws, g_partG[kz] + (size_t)p * 128 * 64, tid);
        grid_sync(++ns);
        {
            const float* gx = g_gatesX + (size_t)t * 4096 * 64;
            float gate[4];
#pragma unroll
            for (int g = 0; g < 4; ++g) {
                int col = np + g;
                float s = g_bpe[col] + gx[(size_t)col * 64 + b];
#pragma unroll
                for (int z = 0; z < 4; ++z) s += g_partG[z][(size_t)col * 64 + b];
                gate[g] = s;
            }
            float c  = g_c[j * 64 + b];
            float cn = sigf(gate[1]) * c + sigf(gate[0]) * tanhf(gate[2]);
            float hn = sigf(gate[3]) * tanhf(cn);
            g_c[j * 64 + b] = cn;
            g_hE[j * 64 + b] = hn;
            if (t == SS - 1) {
                g_dec0[(1024 + j) * 64 + b] = hn;
                g_dec0[j * 64 + b] = x[((size_t)b * SS + SS - 1) * 1024 + j];
            }
        }
        grid_sync(++ns);
    }

    // ---------------- decoder: folded, K=1024 per step (K=2048 at t=0) ----------------
    for (int t = 0; t < SS; ++t) {
        const float* A;
        const float* W;
        int nkt;
        int mprev = (t > 0) ? g_mask[t - 1] : 1;
        if (t == 0) {
            A = g_dec0 + (size_t)(kz * 512) * 64;
            W = g_WTdec + (size_t)(kz * 512) * 4096 + p * 128;
            nkt = 16;
        } else if (mprev) {
            A = g_H + (size_t)(t - 1) * 65536 + (size_t)(kz * 256) * 64;
            W = g_WTdec + (size_t)(1024 + kz * 256) * 4096 + p * 128;
            nkt = 8;
        } else {
            A = g_H + (size_t)(t - 1) * 65536 + (size_t)(kz * 256) * 64;
            W = g_W0 + (size_t)(kz * 256) * 4096 + p * 128;
            nkt = 8;
        }
        gemm_gate(A, W, nkt, As, Ws, g_partG[kz] + (size_t)p * 128 * 64, tid);
        grid_sync(++ns);
        {
            const float* txp = (t > 0 && mprev) ? (g_tgtX + (size_t)(t - 1) * 4096 * 64) : (const float*)0;
            const float* bb  = (t == 0 || mprev) ? g_bpd : g_bfu;
            float gate[4];
#pragma unroll
            for (int g = 0; g < 4; ++g) {
                int col = np + g;
                float s = bb[col];
                if (txp) s += txp[(size_t)col * 64 + b];
#pragma unroll
                for (int z = 0; z < 4; ++z) s += g_partG[z][(size_t)col * 64 + b];
                gate[g] = s;
            }
            float c  = g_c[j * 64 + b];
            float cn = sigf(gate[1]) * c + sigf(gate[0]) * tanhf(gate[2]);
            float hn = sigf(gate[3]) * tanhf(cn);
            g_c[j * 64 + b] = cn;
            g_H[(size_t)t * 65536 + j * 64 + b] = hn;
        }
        grid_sync(++ns);
    }
}

// ============ shared 128x128 K=1024 accumulator (for big_pre) ============
__device__ __forceinline__ void mm128(const float* const rp[4], const float* __restrict__ Wb,
                                      float* As, float* Ws, ull acc[4][8], int tid)
{
    const int tyy = tid >> 4, tx = tid & 15, k4 = tid & 7;
#pragma unroll
    for (int s = 0; s < 4; ++s)
#pragma unroll
        for (int c = 0; c < 8; ++c) acc[s][c] = 0ull;

    float4 pa[4], pw[4];
#pragma unroll
    for (int i = 0; i < 4; ++i) {
        pa[i] = *(const float4*)(rp[i] + k4 * 4);
        int idx = tid + i * 256;
        pw[i] = *(const float4*)(Wb + (size_t)(idx >> 5) * 4096 + (idx & 31) * 4);
    }
    for (int kt = 0; kt < 32; ++kt) {
#pragma unroll
        for (int i = 0; i < 4; ++i) {
            int idx = tid + i * 256;
            int m = idx >> 3, cm = m >> 2;
            const float* e = (const float*)&pa[i];
#pragma unroll
            for (int r = 0; r < 4; ++r) {
                int k = k4 * 4 + r;
                As[k * 128 + ((cm ^ (k >> 2)) << 2) + (m & 3)] = e[r];
            }
            *(float4*)&Ws[(idx >> 5) * 128 + (idx & 31) * 4] = pw[i];
        }
        __syncthreads();
        if (kt + 1 < 32) {
            int kOff = (kt + 1) * 32;
#pragma unroll
            for (int i = 0; i < 4; ++i) {
                pa[i] = *(const float4*)(rp[i] + kOff + k4 * 4);
                int idx = tid + i * 256;
                pw[i] = *(const float4*)(Wb + (size_t)(kOff + (idx >> 5)) * 4096 + (idx & 31) * 4);
            }
        }
#pragma unroll
        for (int kk = 0; kk < 32; ++kk) {
            int sw = kk >> 2;
            ull a[4];
#pragma unroll
            for (int s = 0; s < 4; ++s) {
                int r = tyy + 16 * s;
                a[s] = *(const ull*)&As[kk * 128 + (((r >> 1) ^ sw) << 2) + 2 * (r & 1)];
            }
            float4 wA = *(const float4*)&Ws[kk * 128 + 8 * tx];
            float4 wB = *(const float4*)&Ws[kk * 128 + 8 * tx + 4];
            ull w[8];
            w[0] = dup2(wA.x); w[1] = dup2(wA.y); w[2] = dup2(wA.z); w[3] = dup2(wA.w);
            w[4] = dup2(wB.x); w[5] = dup2(wB.y); w[6] = dup2(wB.z); w[7] = dup2(wB.w);
#pragma unroll
            for (int s = 0; s < 4; ++s)
#pragma unroll
                for (int c = 0; c < 8; ++c)
                    fma2(acc[s][c], a[s], w[c]);
        }
        __syncthreads();
    }
}

// ============ big_pre: zy<256 gatesX, 256..511 tgtX, 512..519 W0, 520 b_fused ============
__global__ __launch_bounds__(256, 1)
void big_pre(const float* __restrict__ x, const float* __restrict__ target,
             const float* __restrict__ fc_b)
{
    __shared__ __align__(16) float As[32 * 128];
    __shared__ __align__(16) float Ws[32 * 128];
    const int tid = threadIdx.x;
    const int zy  = blockIdx.y;
    const int nBase = blockIdx.x * 128;

    if (zy == 520) {                       // b_fused = bpd + Wih_dec @ fc_b (packed)
        int np = blockIdx.x * 256 + tid;
        if (np < 4096) {
            float s = g_bpd[np];
            for (int n = 0; n < 1024; ++n)
                s += g_WTdec[(size_t)n * 4096 + np] * fc_b[n];
            g_bfu[np] = s;
        }
        return;
    }

    const int tyy = tid >> 4, tx = tid & 15;
    ull acc[4][8];
    const float* rp[4];

    if (zy < 512) {
        int z = zy >> 8, tp = zy & 255;
        if (z && !g_mask[2 * tp] && !g_mask[2 * tp + 1]) return;
        const float* src = z ? target : x;
#pragma unroll
        for (int i = 0; i < 4; ++i) {
            int idx = tid + i * 256;
            int mA = idx >> 3;
            rp[i] = src + ((size_t)(mA & 63) * SS + 2 * tp + (mA >> 6)) * 1024;
        }
        mm128(rp, (z ? g_WTdec : g_WTenc) + nBase, As, Ws, acc, tid);
        float* C = z ? g_tgtX : g_gatesX;
#pragma unroll
        for (int s = 0; s < 4; ++s) {
            int m = 2 * (tyy + 16 * s);
            int bb = m & 63, tsel = m >> 6;
            size_t tb = ((size_t)(2 * tp + tsel) * 4096 + nBase + 8 * tx) * 64 + bb;
#pragma unroll
            for (int c = 0; c < 8; ++c) {
                float2 v = unpack2(acc[s][c]);
                *(float2*)&C[tb + (size_t)c * 64] = v;
            }
        }
    } else {
        int mt = zy - 512;
#pragma unroll
        for (int i = 0; i < 4; ++i) {
            int idx = tid + i * 256;
            int mA = idx >> 3;
            rp[i] = g_WTfc + (size_t)(mt * 128 + mA) * 1024;
        }
        mm128(rp, g_WTdec + nBase, As, Ws, acc, tid);
#pragma unroll
        for (int s = 0; s < 4; ++s) {
            int m = 2 * (tyy + 16 * s);
            int j0 = mt * 128 + m;
#pragma unroll
            for (int c = 0; c < 8; ++c) {
                float2 v = unpack2(acc[s][c]);
                int col = nBase + 8 * tx + c;
                g_W0[(size_t)j0 * 4096 + col]       = v.x + g_WTdec[(size_t)(1024 + j0) * 4096 + col];
                g_W0[(size_t)(j0 + 1) * 4096 + col] = v.y + g_WTdec[(size_t)(1025 + j0) * 4096 + col];
            }
        }
    }
}

// ============ preds_out: out[b][t][:] = H[t][:,b] @ fcW^T + fc_b ============
__global__ __launch_bounds__(256, 1)
void preds_out(const float* __restrict__ fc_b, float* __restrict__ out)
{
    __shared__ __align__(16) float As[32 * 128];
    __shared__ __align__(16) float Ws[32 * 128];
    const int tid = threadIdx.x;
    const int nBase = blockIdx.x * 128;
    const int by = blockIdx.y;
    const int tyy = tid >> 4, tx = tid & 15;

    ull acc[4][8];
#pragma unroll
    for (int s = 0; s < 4; ++s)
#pragma unroll
        for (int c = 0; c < 8; ++c) acc[s][c] = 0ull;

    float4 pa[4], pw[4];
#pragma unroll
    for (int i = 0; i < 4; ++i) {
        int idx = tid + i * 256;
        int k = idx >> 5, c4 = idx & 31;
        pa[i] = *(const float4*)(g_H + (size_t)(2 * by + (c4 >> 4)) * 65536 + (size_t)k * 64 + ((c4 * 4) & 63));
        pw[i] = *(const float4*)(g_WTfc + (size_t)k * 1024 + nBase + c4 * 4);
    }
    for (int kt = 0; kt < 32; ++kt) {
#pragma unroll
        for (int i = 0; i < 4; ++i) {
            int idx = tid + i * 256;
            *(float4*)&As[(idx >> 5) * 128 + (idx & 31) * 4] = pa[i];
            *(float4*)&Ws[(idx >> 5) * 128 + (idx & 31) * 4] = pw[i];
        }
        __syncthreads();
        if (kt + 1 < 32) {
            int kOff = (kt + 1) * 32;
#pragma unroll
            for (int i = 0; i < 4; ++i) {
                int idx = tid + i * 256;
                int k = kOff + (idx >> 5), c4 = idx & 31;
                pa[i] = *(const float4*)(g_H + (size_t)(2 * by + (c4 >> 4)) * 65536 + (size_t)k * 64 + ((c4 * 4) & 63));
                pw[i] = *(const float4*)(g_WTfc + (size_t)k * 1024 + nBase + c4 * 4);
            }
        }
#pragma unroll
        for (int kk = 0; kk < 32; ++kk) {
            ull a[4];
#pragma unroll
            for (int s = 0; s < 4; ++s)
                a[s] = *(const ull*)&As[kk * 128 + 2 * (tyy + 16 * s)];
            float4 wA = *(const float4*)&Ws[kk * 128 + 8 * tx];
            float4 wB = *(const float4*)&Ws[kk * 128 + 8 * tx + 4];
            ull w[8];
            w[0] = dup2(wA.x); w[1] = dup2(wA.y); w[2] = dup2(wA.z); w[3] = dup2(wA.w);
            w[4] = dup2(wB.x); w[5] = dup2(wB.y); w[6] = dup2(wB.z); w[7] = dup2(wB.w);
#pragma unroll
            for (int s = 0; s < 4; ++s)
#pragma unroll
                for (int c = 0; c < 8; ++c)
                    fma2(acc[s][c], a[s], w[c]);
        }
        __syncthreads();
    }
    float fcb[8];
#pragma unroll
    for (int c = 0; c < 8; ++c) fcb[c] = fc_b[nBase + 8 * tx + c];
#pragma unroll
    for (int s = 0; s < 4; ++s) {
        int m = 2 * (tyy + 16 * s);
        int t0 = 2 * by + (m >> 6);
        int b0 = m & 63;
        size_t o0 = ((size_t)b0 * SS + t0) * 1024 + nBase + 8 * tx;
        size_t o1 = ((size_t)(b0 + 1) * SS + t0) * 1024 + nBase + 8 * tx;
#pragma unroll
        for (int c = 0; c < 8; c += 2) {
            float2 va = unpack2(acc[s][c]);
            float2 vb = unpack2(acc[s][c + 1]);
            *(float2*)&out[o0 + c] = make_float2(va.x + fcb[c], vb.x + fcb[c + 1]);
            *(float2*)&out[o1 + c] = make_float2(va.y + fcb[c], vb.y + fcb[c + 1]);
        }
    }
}

// ---- fused weight transposes ----
__global__ void tposeAll(const float* __restrict__ eWih, const float* __restrict__ eWhh,
                         const float* __restrict__ dWih, const float* __restrict__ dWhh,
                         const float* __restrict__ fcW)
{
    __shared__ float t[32][33];
    int z = blockIdx.z;
    int k0 = blockIdx.x * 32, n0 = blockIdx.y * 32;
    if (z == 4) {
        if (blockIdx.y >= 32) return;
#pragma unroll
        for (int i = 0; i < 32; i += 8)
            t[threadIdx.y + i][threadIdx.x] = fcW[(size_t)(n0 + threadIdx.y + i) * 1024 + k0 + threadIdx.x];
        __syncthreads();
#pragma unroll
        for (int i = 0; i < 32; i += 8)
            g_WTfc[(size_t)(k0 + threadIdx.y + i) * 1024 + n0 + threadIdx.x] = t[threadIdx.x][threadIdx.y + i];
        return;
    }
    const float* src = (z == 0) ? eWih : (z == 1) ? eWhh : (z == 2) ? dWih : dWhh;
    float* dst = ((z < 2) ? g_WTenc : g_WTdec) + (size_t)(z & 1) * 1024 * 4096;
#pragma unroll
    for (int i = 0; i < 32; i += 8) {
        int np = n0 + threadIdx.y + i;
        int row = ((np & 3) << 10) + (np >> 2);
        t[threadIdx.y + i][threadIdx.x] = src[(size_t)row * 1024 + k0 + threadIdx.x];
    }
    __syncthreads();
#pragma unroll
    for (int i = 0; i < 32; i += 8)
        dst[(size_t)(k0 + threadIdx.y + i) * 4096 + n0 + threadIdx.x] = t[threadIdx.x][threadIdx.y + i];
}

// ---------------- init + mask decode ----------------
__global__ void mask_init(const unsigned char* __restrict__ p,
                          const float* __restrict__ enc_b, const float* __restrict__ dec_b)
{
    int tid = threadIdx.x;
    int i = blockIdx.x * 512 + tid;
    g_c[i] = 0.0f;
    g_hE[i] = 0.0f;
    if (i < 4096) {
        int row = ((i & 3) << 10) + (i >> 2);
        g_bpe[i] = enc_b[row];
        g_bpd[i] = dec_b[row];
    }
    if (blockIdx.x == 1) {
        g_barLeaf[tid] = 0u;
        if (tid == 0) { g_barRoot = 0u; g_barGen = 0u; }
    }
    if (blockIdx.x == 0) {
        __shared__ int s_odd, s_big;
        if (tid == 0) { s_odd = 0; s_big = 0; }
        __syncthreads();
        unsigned char v = p[tid];
        if ((tid & 3) && v)  atomicOr(&s_odd, 1);
        if (v > 1)           atomicOr(&s_big, 1);
        __syncthreads();
        int m;
        if (s_big)        m = (((const float*)p)[tid] != 0.0f);
        else if (s_odd)   m = (p[tid] != 0);
        else              m = (((const int*)p)[tid] != 0);
        g_mask[tid] = m;
    }
}

// ---------------- host ----------------
extern "C" void kernel_launch(void* const* d_in, const int* in_sizes, int n_in,
                              void* d_out, int out_size)
{
    (void)in_sizes; (void)n_in; (void)out_size;
    const float* x       = (const float*)d_in[0];
    const float* target  = (const float*)d_in[1];
    const float* enc_Wih = (const float*)d_in[2];
    const float* enc_Whh = (const float*)d_in[3];
    const float* enc_b   = (const float*)d_in[4];
    const float* dec_Wih = (const float*)d_in[5];
    const float* dec_Whh = (const float*)d_in[6];
    const float* dec_b   = (const float*)d_in[7];
    const float* fc_W    = (const float*)d_in[8];
    const float* fc_b    = (const float*)d_in[9];
    const unsigned char* tf_mask = (const unsigned char*)d_in[10];
    float* out = (float*)d_out;

    // #1: init + mask decode
    mask_init<<<128, 512>>>(tf_mask, enc_b, dec_b);
    // #2: weight transposes
    tposeAll<<<dim3(32, 128, 5), dim3(32, 8)>>>(enc_Wih, enc_Whh, dec_Wih, dec_Whh, fc_W);
    // #3: gatesX + tgtX + W0 + b_fused
    big_pre<<<dim3(32, 521), 256>>>(x, target, fc_b);
    // #4 (profiled): persistent recurrence, 512 threads/CTA
    seq2seq_persist<<<NBLK, 512>>>(x);
    // #5: all predictions post-hoc
    preds_out<<<dim3(8, 256), 256>>>(fc_b, out);
}

// round 13
// speedup vs baseline: 1.0675x; 1.0675x over previous
#include <cuda_runtime.h>
#include <math.h>
#include <stdint.h>

typedef unsigned long long ull;

#define SS 512
#define NBLK 128

// ---------------- device scratch ----------------
__device__ float g_WTenc[2048 * 4096];   // [k][n'=4j+g]; rows 0..1023 Wih^T, 1024..2047 Whh^T
__device__ float g_WTdec[2048 * 4096];
__device__ float g_WTfc [1024 * 1024];   // [k][n] = fcW[n][k]
__device__ float g_W0   [1024 * 4096];   // (Whh + Wih·fcW)^T packed [j][n']
__device__ float g_gatesX[(size_t)512 * 4096 * 64]; // [t][n'][b]
__device__ float g_tgtX  [(size_t)512 * 4096 * 64]; // [t][n'][b]
__device__ float g_H     [(size_t)512 * 1024 * 64]; // decoder h history [t][j][b]
__device__ float g_hB  [3][1024 * 64];   // encoder h triple-buffer [j][b]
__device__ float g_dec0[2048 * 64];      // [x_last | h_enc] [k][b]
__device__ float g_c   [1024 * 64];      // [j][b]
__device__ float g_partG[2][4][4096 * 64]; // gate partials [parity][kz][n'][b]
__device__ float g_bpe[4096], g_bpd[4096], g_bfu[4096];
__device__ int   g_mask[512];
__device__ unsigned g_flagG[128 * 32];   // per-CTA GEMM-done flag, 128B padded
__device__ unsigned g_flagC[128 * 32];   // per-CTA cell-done flag

// ---------------- f32x2 helpers ----------------
__device__ __forceinline__ ull dup2(float v) {
    ull r; unsigned u = __float_as_uint(v);
    asm("mov.b64 %0, {%1, %1};" : "=l"(r) : "r"(u));
    return r;
}
__device__ __forceinline__ void fma2(ull& acc, ull a, ull b) {
    asm("fma.rn.f32x2 %0, %1, %2, %0;" : "+l"(acc) : "l"(a), "l"(b));
}
__device__ __forceinline__ float2 unpack2(ull v) {
    unsigned lo, hi;
    asm("mov.b64 {%0, %1}, %2;" : "=r"(lo), "=r"(hi) : "l"(v));
    return make_float2(__uint_as_float(lo), __uint_as_float(hi));
}
__device__ __forceinline__ float sigf(float x) { return 1.0f / (1.0f + expf(-x)); }

// ---------------- point-to-point flag sync ----------------
// wait until flags[base+i] >= s for i in [0,cnt); one polling thread per flag
__device__ __forceinline__ void wait_flags(const unsigned* f, int base, int cnt,
                                           unsigned s, int tid)
{
    if (tid < cnt) {
        const volatile unsigned* p = (const volatile unsigned*)(f + (size_t)(base + tid) * 32);
        while (*p < s) { }
        __threadfence();
    }
    __syncthreads();
}
// call AFTER __syncthreads(): release own flag
__device__ __forceinline__ void set_flag(unsigned* f, int bid, unsigned s, int tid)
{
    if (tid == 0) {
        __threadfence();
        *(volatile unsigned*)(f + (size_t)bid * 32) = s;
    }
}

// ============ gate GEMM (256 thr): tile 64b x 128n, K-slice, direct partial store ============
__device__ __forceinline__ void gemm_gate(const float* __restrict__ A,
                                          const float* __restrict__ Wp,
                                          int nKT, float* As, float* Ws,
                                          float* __restrict__ dst, int tid)
{
    const int ty = tid >> 5, tx = tid & 31;
    ull acc[4][4];
#pragma unroll
    for (int q = 0; q < 4; ++q)
#pragma unroll
        for (int c = 0; c < 4; ++c) acc[q][c] = 0ull;

    float4 pa[2], pw[4];
#pragma unroll
    for (int i = 0; i < 2; ++i) {
        int idx = tid + i * 256;
        pa[i] = *(const float4*)(A + (size_t)(idx >> 4) * 64 + (idx & 15) * 4);
    }
#pragma unroll
    for (int i = 0; i < 4; ++i) {
        int idx = tid + i * 256;
        pw[i] = *(const float4*)(Wp + (size_t)(idx >> 5) * 4096 + (idx & 31) * 4);
    }

    for (int kt = 0; kt < nKT; ++kt) {
#pragma unroll
        for (int i = 0; i < 2; ++i) {
            int idx = tid + i * 256;
            *(float4*)&As[(idx >> 4) * 64 + (idx & 15) * 4] = pa[i];
        }
#pragma unroll
        for (int i = 0; i < 4; ++i) {
            int idx = tid + i * 256;
            *(float4*)&Ws[(idx >> 5) * 128 + (idx & 31) * 4] = pw[i];
        }
        __syncthreads();
        if (kt + 1 < nKT) {
            int kOff = (kt + 1) * 32;
#pragma unroll
            for (int i = 0; i < 2; ++i) {
                int idx = tid + i * 256;
                pa[i] = *(const float4*)(A + (size_t)(kOff + (idx >> 4)) * 64 + (idx & 15) * 4);
            }
#pragma unroll
            for (int i = 0; i < 4; ++i) {
                int idx = tid + i * 256;
                pw[i] = *(const float4*)(Wp + (size_t)(kOff + (idx >> 5)) * 4096 + (idx & 31) * 4);
            }
        }
#pragma unroll
        for (int kk = 0; kk < 32; ++kk) {
            ulonglong2 aa = *(const ulonglong2*)&As[kk * 64 + 8 * ty];
            ulonglong2 ab = *(const ulonglong2*)&As[kk * 64 + 8 * ty + 4];
            float4 wv = *(const float4*)&Ws[kk * 128 + 4 * tx];
            ull w0 = dup2(wv.x), w1 = dup2(wv.y), w2 = dup2(wv.z), w3 = dup2(wv.w);
            fma2(acc[0][0], aa.x, w0); fma2(acc[0][1], aa.x, w1);
            fma2(acc[0][2], aa.x, w2); fma2(acc[0][3], aa.x, w3);
            fma2(acc[1][0], aa.y, w0); fma2(acc[1][1], aa.y, w1);
            fma2(acc[1][2], aa.y, w2); fma2(acc[1][3], aa.y, w3);
            fma2(acc[2][0], ab.x, w0); fma2(acc[2][1], ab.x, w1);
            fma2(acc[2][2], ab.x, w2); fma2(acc[2][3], ab.x, w3);
            fma2(acc[3][0], ab.y, w0); fma2(acc[3][1], ab.y, w1);
            fma2(acc[3][2], ab.y, w2); fma2(acc[3][3], ab.y, w3);
        }
        __syncthreads();
    }
#pragma unroll
    for (int q = 0; q < 4; ++q)
#pragma unroll
        for (int c = 0; c < 4; ++c) {
            float2 v = unpack2(acc[q][c]);
            *(float2*)&dst[(4 * tx + c) * 64 + 8 * ty + 2 * q] = v;
        }
}

// ============ persistent kernel: 128 CTAs x 256 threads, flag dataflow ============
__global__ __launch_bounds__(256, 1)
void seq2seq_persist(const float* __restrict__ x)
{
    __shared__ __align__(16) float As[32 * 64];
    __shared__ __align__(16) float Ws[32 * 128];

    const int tid = threadIdx.x;
    const int bid = blockIdx.x;
    const int p   = bid >> 2;     // 32 n-tiles of 128 cols
    const int kz  = bid & 3;      // K quarter
    const int qb  = (bid >> 2) * 4;

    // ---------------- encoder (steps s = 1..512) ----------------
    for (int t = 0; t < SS; ++t) {
        unsigned s = (unsigned)(t + 1);
        // GEMM needs h rows [kz*256, kz*256+256) from cells of step s-1
        wait_flags(g_flagC, kz * 32, 32, s - 1, tid);
        gemm_gate(g_hB[(s - 1) % 3] + (size_t)(kz * 256) * 64,
                  g_WTenc + (size_t)(1024 + kz * 256) * 4096 + p * 128,
                  8, As, Ws, g_partG[s & 1][kz] + (size_t)p * 128 * 64, tid);
        __syncthreads();
        set_flag(g_flagG, bid, s, tid);
        // cell needs partials from own quad
        wait_flags(g_flagG, qb, 4, s, tid);
        {
            const int par = s & 1;
            const float* gx = g_gatesX + (size_t)t * 4096 * 64;
#pragma unroll
            for (int r = 0; r < 2; ++r) {
                int id = bid * 512 + r * 256 + tid;
                int b = id & 63, j = id >> 6, np = 4 * j;
                float gate[4];
#pragma unroll
                for (int g = 0; g < 4; ++g) {
                    int col = np + g;
                    float sm = g_bpe[col] + gx[(size_t)col * 64 + b];
#pragma unroll
                    for (int z = 0; z < 4; ++z)
                        sm += g_partG[par][z][(size_t)col * 64 + b];
                    gate[g] = sm;
                }
                float c  = g_c[j * 64 + b];
                float cn = sigf(gate[1]) * c + sigf(gate[0]) * tanhf(gate[2]);
                float hn = sigf(gate[3]) * tanhf(cn);
                g_c[j * 64 + b] = cn;
                g_hB[s % 3][j * 64 + b] = hn;
                if (t == SS - 1) {
                    g_dec0[(1024 + j) * 64 + b] = hn;
                    g_dec0[j * 64 + b] = x[((size_t)b * SS + SS - 1) * 1024 + j];
                }
            }
        }
        __syncthreads();
        set_flag(g_flagC, bid, s, tid);
    }

    // ---------------- decoder (steps s = 513..1024) ----------------
    for (int t = 0; t < SS; ++t) {
        unsigned s = (unsigned)(SS + t + 1);
        const float* A;
        const float* W;
        int nkt;
        int mprev = (t > 0) ? g_mask[t - 1] : 1;
        if (t == 0) {
            wait_flags(g_flagC, 0, 128, SS, tid);       // dec0 needs ALL cells of s=512
            A = g_dec0 + (size_t)(kz * 512) * 64;
            W = g_WTdec + (size_t)(kz * 512) * 4096 + p * 128;
            nkt = 16;
        } else {
            wait_flags(g_flagC, kz * 32, 32, s - 1, tid);
            A = g_H + (size_t)(t - 1) * 65536 + (size_t)(kz * 256) * 64;
            if (mprev) W = g_WTdec + (size_t)(1024 + kz * 256) * 4096 + p * 128;
            else       W = g_W0 + (size_t)(kz * 256) * 4096 + p * 128;
            nkt = 8;
        }
        gemm_gate(A, W, nkt, As, Ws, g_partG[s & 1][kz] + (size_t)p * 128 * 64, tid);
        __syncthreads();
        set_flag(g_flagG, bid, s, tid);
        wait_flags(g_flagG, qb, 4, s, tid);
        {
            const int par = s & 1;
            const float* txp = (t > 0 && mprev) ? (g_tgtX + (size_t)(t - 1) * 4096 * 64) : (const float*)0;
            const float* bb  = (t == 0 || mprev) ? g_bpd : g_bfu;
#pragma unroll
            for (int r = 0; r < 2; ++r) {
                int id = bid * 512 + r * 256 + tid;
                int b = id & 63, j = id >> 6, np = 4 * j;
                float gate[4];
#pragma unroll
                for (int g = 0; g < 4; ++g) {
                    int col = np + g;
                    float sm = bb[col];
                    if (txp) sm += txp[(size_t)col * 64 + b];
#pragma unroll
                    for (int z = 0; z < 4; ++z)
                        sm += g_partG[par][z][(size_t)col * 64 + b];
                    gate[g] = sm;
                }
                float c  = g_c[j * 64 + b];
                float cn = sigf(gate[1]) * c + sigf(gate[0]) * tanhf(gate[2]);
                float hn = sigf(gate[3]) * tanhf(cn);
                g_c[j * 64 + b] = cn;
                g_H[(size_t)t * 65536 + j * 64 + b] = hn;
            }
        }
        __syncthreads();
        set_flag(g_flagC, bid, s, tid);
    }
}

// ============ shared 128x128 K=1024 accumulator (for big_pre) ============
__device__ __forceinline__ void mm128(const float* const rp[4], const float* __restrict__ Wb,
                                      float* As, float* Ws, ull acc[4][8], int tid)
{
    const int tyy = tid >> 4, tx = tid & 15, k4 = tid & 7;
#pragma unroll
    for (int s = 0; s < 4; ++s)
#pragma unroll
        for (int c = 0; c < 8; ++c) acc[s][c] = 0ull;

    float4 pa[4], pw[4];
#pragma unroll
    for (int i = 0; i < 4; ++i) {
        pa[i] = *(const float4*)(rp[i] + k4 * 4);
        int idx = tid + i * 256;
        pw[i] = *(const float4*)(Wb + (size_t)(idx >> 5) * 4096 + (idx & 31) * 4);
    }
    for (int kt = 0; kt < 32; ++kt) {
#pragma unroll
        for (int i = 0; i < 4; ++i) {
            int idx = tid + i * 256;
            int m = idx >> 3, cm = m >> 2;
            const float* e = (const float*)&pa[i];
#pragma unroll
            for (int r = 0; r < 4; ++r) {
                int k = k4 * 4 + r;
                As[k * 128 + ((cm ^ (k >> 2)) << 2) + (m & 3)] = e[r];
            }
            *(float4*)&Ws[(idx >> 5) * 128 + (idx & 31) * 4] = pw[i];
        }
        __syncthreads();
        if (kt + 1 < 32) {
            int kOff = (kt + 1) * 32;
#pragma unroll
            for (int i = 0; i < 4; ++i) {
                pa[i] = *(const float4*)(rp[i] + kOff + k4 * 4);
                int idx = tid + i * 256;
                pw[i] = *(const float4*)(Wb + (size_t)(kOff + (idx >> 5)) * 4096 + (idx & 31) * 4);
            }
        }
#pragma unroll
        for (int kk = 0; kk < 32; ++kk) {
            int sw = kk >> 2;
            ull a[4];
#pragma unroll
            for (int s = 0; s < 4; ++s) {
                int r = tyy + 16 * s;
                a[s] = *(const ull*)&As[kk * 128 + (((r >> 1) ^ sw) << 2) + 2 * (r & 1)];
            }
            float4 wA = *(const float4*)&Ws[kk * 128 + 8 * tx];
            float4 wB = *(const float4*)&Ws[kk * 128 + 8 * tx + 4];
            ull w[8];
            w[0] = dup2(wA.x); w[1] = dup2(wA.y); w[2] = dup2(wA.z); w[3] = dup2(wA.w);
            w[4] = dup2(wB.x); w[5] = dup2(wB.y); w[6] = dup2(wB.z); w[7] = dup2(wB.w);
#pragma unroll
            for (int s = 0; s < 4; ++s)
#pragma unroll
                for (int c = 0; c < 8; ++c)
                    fma2(acc[s][c], a[s], w[c]);
        }
        __syncthreads();
    }
}

// ============ big_pre: zy<256 gatesX, 256..511 tgtX, 512..519 W0, 520 b_fused ============
__global__ __launch_bounds__(256, 1)
void big_pre(const float* __restrict__ x, const float* __restrict__ target,
             const float* __restrict__ fc_b)
{
    __shared__ __align__(16) float As[32 * 128];
    __shared__ __align__(16) float Ws[32 * 128];
    const int tid = threadIdx.x;
    const int zy  = blockIdx.y;
    const int nBase = blockIdx.x * 128;

    if (zy == 520) {
        int np = blockIdx.x * 256 + tid;
        if (np < 4096) {
            float s = g_bpd[np];
            for (int n = 0; n < 1024; ++n)
                s += g_WTdec[(size_t)n * 4096 + np] * fc_b[n];
            g_bfu[np] = s;
        }
        return;
    }

    const int tyy = tid >> 4, tx = tid & 15;
    ull acc[4][8];
    const float* rp[4];

    if (zy < 512) {
        int z = zy >> 8, tp = zy & 255;
        if (z && !g_mask[2 * tp] && !g_mask[2 * tp + 1]) return;
        const float* src = z ? target : x;
#pragma unroll
        for (int i = 0; i < 4; ++i) {
            int idx = tid + i * 256;
            int mA = idx >> 3;
            rp[i] = src + ((size_t)(mA & 63) * SS + 2 * tp + (mA >> 6)) * 1024;
        }
        mm128(rp, (z ? g_WTdec : g_WTenc) + nBase, As, Ws, acc, tid);
        float* C = z ? g_tgtX : g_gatesX;
#pragma unroll
        for (int s = 0; s < 4; ++s) {
            int m = 2 * (tyy + 16 * s);
            int bb = m & 63, tsel = m >> 6;
            size_t tb = ((size_t)(2 * tp + tsel) * 4096 + nBase + 8 * tx) * 64 + bb;
#pragma unroll
            for (int c = 0; c < 8; ++c) {
                float2 v = unpack2(acc[s][c]);
                *(float2*)&C[tb + (size_t)c * 64] = v;
            }
        }
    } else {
        int mt = zy - 512;
#pragma unroll
        for (int i = 0; i < 4; ++i) {
            int idx = tid + i * 256;
            int mA = idx >> 3;
            rp[i] = g_WTfc + (size_t)(mt * 128 + mA) * 1024;
        }
        mm128(rp, g_WTdec + nBase, As, Ws, acc, tid);
#pragma unroll
        for (int s = 0; s < 4; ++s) {
            int m = 2 * (tyy + 16 * s);
            int j0 = mt * 128 + m;
#pragma unroll
            for (int c = 0; c < 8; ++c) {
                float2 v = unpack2(acc[s][c]);
                int col = nBase + 8 * tx + c;
                g_W0[(size_t)j0 * 4096 + col]       = v.x + g_WTdec[(size_t)(1024 + j0) * 4096 + col];
                g_W0[(size_t)(j0 + 1) * 4096 + col] = v.y + g_WTdec[(size_t)(1025 + j0) * 4096 + col];
            }
        }
    }
}

// ============ preds_out: out[b][t][:] = H[t][:,b] @ fcW^T + fc_b ============
__global__ __launch_bounds__(256, 1)
void preds_out(const float* __restrict__ fc_b, float* __restrict__ out)
{
    __shared__ __align__(16) float As[32 * 128];
    __shared__ __align__(16) float Ws[32 * 128];
    const int tid = threadIdx.x;
    const int nBase = blockIdx.x * 128;
    const int by = blockIdx.y;
    const int tyy = tid >> 4, tx = tid & 15;

    ull acc[4][8];
#pragma unroll
    for (int s = 0; s < 4; ++s)
#pragma unroll
        for (int c = 0; c < 8; ++c) acc[s][c] = 0ull;

    float4 pa[4], pw[4];
#pragma unroll
    for (int i = 0; i < 4; ++i) {
        int idx = tid + i * 256;
        int k = idx >> 5, c4 = idx & 31;
        pa[i] = *(const float4*)(g_H + (size_t)(2 * by + (c4 >> 4)) * 65536 + (size_t)k * 64 + ((c4 * 4) & 63));
        pw[i] = *(const float4*)(g_WTfc + (size_t)k * 1024 + nBase + c4 * 4);
    }
    for (int kt = 0; kt < 32; ++kt) {
#pragma unroll
        for (int i = 0; i < 4; ++i) {
            int idx = tid + i * 256;
            *(float4*)&As[(idx >> 5) * 128 + (idx & 31) * 4] = pa[i];
            *(float4*)&Ws[(idx >> 5) * 128 + (idx & 31) * 4] = pw[i];
        }
        __syncthreads();
        if (kt + 1 < 32) {
            int kOff = (kt + 1) * 32;
#pragma unroll
            for (int i = 0; i < 4; ++i) {
                int idx = tid + i * 256;
                int k = kOff + (idx >> 5), c4 = idx & 31;
                pa[i] = *(const float4*)(g_H + (size_t)(2 * by + (c4 >> 4)) * 65536 + (size_t)k * 64 + ((c4 * 4) & 63));
                pw[i] = *(const float4*)(g_WTfc + (size_t)k * 1024 + nBase + c4 * 4);
            }
        }
#pragma unroll
        for (int kk = 0; kk < 32; ++kk) {
            ull a[4];
#pragma unroll
            for (int s = 0; s < 4; ++s)
                a[s] = *(const ull*)&As[kk * 128 + 2 * (tyy + 16 * s)];
            float4 wA = *(const float4*)&Ws[kk * 128 + 8 * tx];
            float4 wB = *(const float4*)&Ws[kk * 128 + 8 * tx + 4];
            ull w[8];
            w[0] = dup2(wA.x); w[1] = dup2(wA.y); w[2] = dup2(wA.z); w[3] = dup2(wA.w);
            w[4] = dup2(wB.x); w[5] = dup2(wB.y); w[6] = dup2(wB.z); w[7] = dup2(wB.w);
#pragma unroll
            for (int s = 0; s < 4; ++s)
#pragma unroll
                for (int c = 0; c < 8; ++c)
                    fma2(acc[s][c], a[s], w[c]);
        }
        __syncthreads();
    }
    float fcb[8];
#pragma unroll
    for (int c = 0; c < 8; ++c) fcb[c] = fc_b[nBase + 8 * tx + c];
#pragma unroll
    for (int s = 0; s < 4; ++s) {
        int m = 2 * (tyy + 16 * s);
        int t0 = 2 * by + (m >> 6);
        int b0 = m & 63;
        size_t o0 = ((size_t)b0 * SS + t0) * 1024 + nBase + 8 * tx;
        size_t o1 = ((size_t)(b0 + 1) * SS + t0) * 1024 + nBase + 8 * tx;
#pragma unroll
        for (int c = 0; c < 8; c += 2) {
            float2 va = unpack2(acc[s][c]);
            float2 vb = unpack2(acc[s][c + 1]);
            *(float2*)&out[o0 + c] = make_float2(va.x + fcb[c], vb.x + fcb[c + 1]);
            *(float2*)&out[o1 + c] = make_float2(va.y + fcb[c], vb.y + fcb[c + 1]);
        }
    }
}

// ---- fused weight transposes ----
__global__ void tposeAll(const float* __restrict__ eWih, const float* __restrict__ eWhh,
                         const float* __restrict__ dWih, const float* __restrict__ dWhh,
                         const float* __restrict__ fcW)
{
    __shared__ float t[32][33];
    int z = blockIdx.z;
    int k0 = blockIdx.x * 32, n0 = blockIdx.y * 32;
    if (z == 4) {
        if (blockIdx.y >= 32) return;
#pragma unroll
        for (int i = 0; i < 32; i += 8)
            t[threadIdx.y + i][threadIdx.x] = fcW[(size_t)(n0 + threadIdx.y + i) * 1024 + k0 + threadIdx.x];
        __syncthreads();
#pragma unroll
        for (int i = 0; i < 32; i += 8)
            g_WTfc[(size_t)(k0 + threadIdx.y + i) * 1024 + n0 + threadIdx.x] = t[threadIdx.x][threadIdx.y + i];
        return;
    }
    const float* src = (z == 0) ? eWih : (z == 1) ? eWhh : (z == 2) ? dWih : dWhh;
    float* dst = ((z < 2) ? g_WTenc : g_WTdec) + (size_t)(z & 1) * 1024 * 4096;
#pragma unroll
    for (int i = 0; i < 32; i += 8) {
        int np = n0 + threadIdx.y + i;
        int row = ((np & 3) << 10) + (np >> 2);
        t[threadIdx.y + i][threadIdx.x] = src[(size_t)row * 1024 + k0 + threadIdx.x];
    }
    __syncthreads();
#pragma unroll
    for (int i = 0; i < 32; i += 8)
        dst[(size_t)(k0 + threadIdx.y + i) * 4096 + n0 + threadIdx.x] = t[threadIdx.x][threadIdx.y + i];
}

// ---------------- init + mask decode ----------------
__global__ void mask_init(const unsigned char* __restrict__ p,
                          const float* __restrict__ enc_b, const float* __restrict__ dec_b)
{
    int tid = threadIdx.x;
    int i = blockIdx.x * 512 + tid;
    g_c[i] = 0.0f;
    g_hB[0][i] = 0.0f;
    if (i < 4096) {
        int row = ((i & 3) << 10) + (i >> 2);
        g_bpe[i] = enc_b[row];
        g_bpd[i] = dec_b[row];
    }
    if (blockIdx.x == 2) {
#pragma unroll
        for (int k = 0; k < 8; ++k) g_flagG[tid + 512 * k] = 0u;
    }
    if (blockIdx.x == 3) {
#pragma unroll
        for (int k = 0; k < 8; ++k) g_flagC[tid + 512 * k] = 0u;
    }
    if (blockIdx.x == 0) {
        __shared__ int s_odd, s_big;
        if (tid == 0) { s_odd = 0; s_big = 0; }
        __syncthreads();
        unsigned char v = p[tid];
        if ((tid & 3) && v)  atomicOr(&s_odd, 1);
        if (v > 1)           atomicOr(&s_big, 1);
        __syncthreads();
        int m;
        if (s_big)        m = (((const float*)p)[tid] != 0.0f);
        else if (s_odd)   m = (p[tid] != 0);
        else              m = (((const int*)p)[tid] != 0);
        g_mask[tid] = m;
    }
}

// ---------------- host ----------------
extern "C" void kernel_launch(void* const* d_in, const int* in_sizes, int n_in,
                              void* d_out, int out_size)
{
    (void)in_sizes; (void)n_in; (void)out_size;
    const float* x       = (const float*)d_in[0];
    const float* target  = (const float*)d_in[1];
    const float* enc_Wih = (const float*)d_in[2];
    const float* enc_Whh = (const float*)d_in[3];
    const float* enc_b   = (const float*)d_in[4];
    const float* dec_Wih = (const float*)d_in[5];
    const float* dec_Whh = (const float*)d_in[6];
    const float* dec_b   = (const float*)d_in[7];
    const float* fc_W    = (const float*)d_in[8];
    const float* fc_b    = (const float*)d_in[9];
    const unsigned char* tf_mask = (const unsigned char*)d_in[10];
    float* out = (float*)d_out;

    // #1: init + mask decode (+ flag reset)
    mask_init<<<128, 512>>>(tf_mask, enc_b, dec_b);
    // #2: weight transposes
    tposeAll<<<dim3(32, 128, 5), dim3(32, 8)>>>(enc_Wih, enc_Whh, dec_Wih, dec_Whh, fc_W);
    // #3: gatesX + tgtX + W0 + b_fused
    big_pre<<<dim3(32, 521), 256>>>(x, target, fc_b);
    // #4 (profiled): persistent recurrence, flag dataflow
    seq2seq_persist<<<NBLK, 256>>>(x);
    // #5: all predictions post-hoc
    preds_out<<<dim3(8, 256), 256>>>(fc_b, out);
}

// round 14
// speedup vs baseline: 1.1424x; 1.0701x over previous
#include <cuda_runtime.h>
#include <math.h>
#include <stdint.h>

typedef unsigned long long ull;

#define SS 512
#define NBLK 128
// dynamic smem layout (floats): [0,32768) resident W, [32768,36864) A dbuf, [36864,40960) W stream
#define SMEM_FLOATS 40960
#define SMEM_BYTES  (SMEM_FLOATS * 4)

// ---------------- device scratch ----------------
__device__ float g_WTenc[2048 * 4096];   // [k][n'=4j+g]; rows 0..1023 Wih^T, 1024..2047 Whh^T
__device__ float g_WTdec[2048 * 4096];
__device__ float g_WTfc [1024 * 1024];   // [k][n] = fcW[n][k]
__device__ float g_W0   [1024 * 4096];   // (Whh + Wih·fcW)^T packed [j][n']
__device__ float g_gatesX[(size_t)512 * 4096 * 64]; // [t][n'][b]
__device__ float g_tgtX  [(size_t)512 * 4096 * 64]; // [t][n'][b]
__device__ float g_H     [(size_t)512 * 1024 * 64]; // decoder h history [t][j][b]
__device__ float g_hB  [3][1024 * 64];   // encoder h triple-buffer [j][b]
__device__ float g_dec0[2048 * 64];      // [x_last | h_enc] [k][b]
__device__ float g_c   [1024 * 64];      // [j][b]
__device__ float g_partG[2][4][4096 * 64]; // gate partials [parity][kz][n'][b]
__device__ float g_bpe[4096], g_bpd[4096], g_bfu[4096];
__device__ int   g_mask[512];
__device__ unsigned g_flagG[128 * 32];   // per-CTA GEMM-done flag, 128B padded
__device__ unsigned g_flagC[128 * 32];   // per-CTA cell-done flag

// ---------------- f32x2 helpers ----------------
__device__ __forceinline__ ull dup2(float v) {
    ull r; unsigned u = __float_as_uint(v);
    asm("mov.b64 %0, {%1, %1};" : "=l"(r) : "r"(u));
    return r;
}
__device__ __forceinline__ void fma2(ull& acc, ull a, ull b) {
    asm("fma.rn.f32x2 %0, %1, %2, %0;" : "+l"(acc) : "l"(a), "l"(b));
}
__device__ __forceinline__ float2 unpack2(ull v) {
    unsigned lo, hi;
    asm("mov.b64 {%0, %1}, %2;" : "=r"(lo), "=r"(hi) : "l"(v));
    return make_float2(__uint_as_float(lo), __uint_as_float(hi));
}
__device__ __forceinline__ float sigf(float x) { return 1.0f / (1.0f + expf(-x)); }

// ---------------- point-to-point flag sync ----------------
__device__ __forceinline__ void wait_flags(const unsigned* f, int base, int cnt,
                                           unsigned s, int tid)
{
    if (tid < cnt) {
        const volatile unsigned* p = (const volatile unsigned*)(f + (size_t)(base + tid) * 32);
        while (*p < s) { }
        __threadfence();
    }
    __syncthreads();
}
__device__ __forceinline__ void set_flag(unsigned* f, int bid, unsigned s, int tid)
{
    if (tid == 0) {
        __threadfence();
        *(volatile unsigned*)(f + (size_t)bid * 32) = s;
    }
}

// ============ resident-W gate GEMM: W in SMEM for the whole phase ============
// tile 64b x 128n; A (h) staged 8KB/kt double-buffered, ONE sync per kt.
__device__ __forceinline__ void gemm_res(const float* __restrict__ A,
                                         const float* __restrict__ Wres,  // [kt*32+kk][128]
                                         int nKT, float* Ab,
                                         float* __restrict__ dst, int tid)
{
    const int ty = tid >> 5, tx = tid & 31;
    ull acc[4][4];
#pragma unroll
    for (int q = 0; q < 4; ++q)
#pragma unroll
        for (int c = 0; c < 4; ++c) acc[q][c] = 0ull;

    float4 pa[2];
#pragma unroll
    for (int i = 0; i < 2; ++i) {
        int idx = tid + i * 256;
        pa[i] = *(const float4*)(A + (size_t)(idx >> 4) * 64 + (idx & 15) * 4);
    }
#pragma unroll
    for (int i = 0; i < 2; ++i) {
        int idx = tid + i * 256;
        *(float4*)&Ab[(idx >> 4) * 64 + (idx & 15) * 4] = pa[i];
    }
    __syncthreads();

    for (int kt = 0; kt < nKT; ++kt) {
        const int cb = kt & 1;
        const float* Ac = Ab + cb * 2048;
        const float* Wk = Wres + kt * (32 * 128);
        const bool more = (kt + 1 < nKT);
        if (more) {
            int kOff = (kt + 1) * 32;
#pragma unroll
            for (int i = 0; i < 2; ++i) {
                int idx = tid + i * 256;
                pa[i] = *(const float4*)(A + (size_t)(kOff + (idx >> 4)) * 64 + (idx & 15) * 4);
            }
        }
#pragma unroll
        for (int kk = 0; kk < 32; ++kk) {
            ulonglong2 aa = *(const ulonglong2*)&Ac[kk * 64 + 8 * ty];
            ulonglong2 ab = *(const ulonglong2*)&Ac[kk * 64 + 8 * ty + 4];
            float4 wv = *(const float4*)&Wk[kk * 128 + 4 * tx];
            ull w0 = dup2(wv.x), w1 = dup2(wv.y), w2 = dup2(wv.z), w3 = dup2(wv.w);
            fma2(acc[0][0], aa.x, w0); fma2(acc[0][1], aa.x, w1);
            fma2(acc[0][2], aa.x, w2); fma2(acc[0][3], aa.x, w3);
            fma2(acc[1][0], aa.y, w0); fma2(acc[1][1], aa.y, w1);
            fma2(acc[1][2], aa.y, w2); fma2(acc[1][3], aa.y, w3);
            fma2(acc[2][0], ab.x, w0); fma2(acc[2][1], ab.x, w1);
            fma2(acc[2][2], ab.x, w2); fma2(acc[2][3], ab.x, w3);
            fma2(acc[3][0], ab.y, w0); fma2(acc[3][1], ab.y, w1);
            fma2(acc[3][2], ab.y, w2); fma2(acc[3][3], ab.y, w3);
        }
        if (more) {
            float* An = Ab + (cb ^ 1) * 2048;
#pragma unroll
            for (int i = 0; i < 2; ++i) {
                int idx = tid + i * 256;
                *(float4*)&An[(idx >> 4) * 64 + (idx & 15) * 4] = pa[i];
            }
        }
        __syncthreads();
    }
#pragma unroll
    for (int q = 0; q < 4; ++q)
#pragma unroll
        for (int c = 0; c < 4; ++c) {
            float2 v = unpack2(acc[q][c]);
            *(float2*)&dst[(4 * tx + c) * 64 + 8 * ty + 2 * q] = v;
        }
}

// ============ streamed gate GEMM (t=0 and mask=0 steps) — R13 version ============
__device__ __forceinline__ void gemm_stream(const float* __restrict__ A,
                                            const float* __restrict__ Wp,
                                            int nKT, float* As, float* Ws,
                                            float* __restrict__ dst, int tid)
{
    const int ty = tid >> 5, tx = tid & 31;
    ull acc[4][4];
#pragma unroll
    for (int q = 0; q < 4; ++q)
#pragma unroll
        for (int c = 0; c < 4; ++c) acc[q][c] = 0ull;

    float4 pa[2], pw[4];
#pragma unroll
    for (int i = 0; i < 2; ++i) {
        int idx = tid + i * 256;
        pa[i] = *(const float4*)(A + (size_t)(idx >> 4) * 64 + (idx & 15) * 4);
    }
#pragma unroll
    for (int i = 0; i < 4; ++i) {
        int idx = tid + i * 256;
        pw[i] = *(const float4*)(Wp + (size_t)(idx >> 5) * 4096 + (idx & 31) * 4);
    }

    for (int kt = 0; kt < nKT; ++kt) {
#pragma unroll
        for (int i = 0; i < 2; ++i) {
            int idx = tid + i * 256;
            *(float4*)&As[(idx >> 4) * 64 + (idx & 15) * 4] = pa[i];
        }
#pragma unroll
        for (int i = 0; i < 4; ++i) {
            int idx = tid + i * 256;
            *(float4*)&Ws[(idx >> 5) * 128 + (idx & 31) * 4] = pw[i];
        }
        __syncthreads();
        if (kt + 1 < nKT) {
            int kOff = (kt + 1) * 32;
#pragma unroll
            for (int i = 0; i < 2; ++i) {
                int idx = tid + i * 256;
                pa[i] = *(const float4*)(A + (size_t)(kOff + (idx >> 4)) * 64 + (idx & 15) * 4);
            }
#pragma unroll
            for (int i = 0; i < 4; ++i) {
                int idx = tid + i * 256;
                pw[i] = *(const float4*)(Wp + (size_t)(kOff + (idx >> 5)) * 4096 + (idx & 31) * 4);
            }
        }
#pragma unroll
        for (int kk = 0; kk < 32; ++kk) {
            ulonglong2 aa = *(const ulonglong2*)&As[kk * 64 + 8 * ty];
            ulonglong2 ab = *(const ulonglong2*)&As[kk * 64 + 8 * ty + 4];
            float4 wv = *(const float4*)&Ws[kk * 128 + 4 * tx];
            ull w0 = dup2(wv.x), w1 = dup2(wv.y), w2 = dup2(wv.z), w3 = dup2(wv.w);
            fma2(acc[0][0], aa.x, w0); fma2(acc[0][1], aa.x, w1);
            fma2(acc[0][2], aa.x, w2); fma2(acc[0][3], aa.x, w3);
            fma2(acc[1][0], aa.y, w0); fma2(acc[1][1], aa.y, w1);
            fma2(acc[1][2], aa.y, w2); fma2(acc[1][3], aa.y, w3);
            fma2(acc[2][0], ab.x, w0); fma2(acc[2][1], ab.x, w1);
            fma2(acc[2][2], ab.x, w2); fma2(acc[2][3], ab.x, w3);
            fma2(acc[3][0], ab.y, w0); fma2(acc[3][1], ab.y, w1);
            fma2(acc[3][2], ab.y, w2); fma2(acc[3][3], ab.y, w3);
        }
        __syncthreads();
    }
#pragma unroll
    for (int q = 0; q < 4; ++q)
#pragma unroll
        for (int c = 0; c < 4; ++c) {
            float2 v = unpack2(acc[q][c]);
            *(float2*)&dst[(4 * tx + c) * 64 + 8 * ty + 2 * q] = v;
        }
}

// ---- load a 256k x 128col weight slice into resident SMEM ----
__device__ __forceinline__ void load_wres(float* Wres, const float* __restrict__ Wsrc, int tid)
{
    for (int r = tid; r < 8192; r += 256)       // 8192 float4
        ((float4*)Wres)[r] = *(const float4*)(Wsrc + (size_t)(r >> 5) * 4096 + (r & 31) * 4);
    __syncthreads();
}

// ============ persistent kernel: 128 CTAs x 256 threads, flag dataflow + resident W ============
__global__ __launch_bounds__(256, 1)
void seq2seq_persist(const float* __restrict__ x)
{
    extern __shared__ __align__(16) float smem[];
    float* Wres = smem;                 // 32768 floats
    float* Ab   = smem + 32768;         // 4096 floats (2x 8KB A buffers)
    float* Wstr = smem + 36864;         // 4096 floats (streamed W tile)

    const int tid = threadIdx.x;
    const int bid = blockIdx.x;
    const int p   = bid >> 2;     // 32 n-tiles of 128 cols
    const int kz  = bid & 3;      // K quarter
    const int qb  = (bid >> 2) * 4;

    // resident encoder Whh slice
    load_wres(Wres, g_WTenc + (size_t)(1024 + kz * 256) * 4096 + p * 128, tid);

    // ---------------- encoder (steps s = 1..512) ----------------
    for (int t = 0; t < SS; ++t) {
        unsigned s = (unsigned)(t + 1);
        wait_flags(g_flagC, kz * 32, 32, s - 1, tid);
        gemm_res(g_hB[(s - 1) % 3] + (size_t)(kz * 256) * 64, Wres,
                 8, Ab, g_partG[s & 1][kz] + (size_t)p * 128 * 64, tid);
        set_flag(g_flagG, bid, s, tid);
        // prefetch gatesX + bias while waiting for quad partials
        float gxa[2][4], bbv[2][4];
        {
            const float* gx = g_gatesX + (size_t)t * 4096 * 64;
#pragma unroll
            for (int r = 0; r < 2; ++r) {
                int id = bid * 512 + r * 256 + tid;
                int b = id & 63, np = (id >> 6) * 4;
                const float* gp = gx + (size_t)np * 64 + b;
                gxa[r][0] = gp[0];   gxa[r][1] = gp[64];
                gxa[r][2] = gp[128]; gxa[r][3] = gp[192];
                float4 bv = *(const float4*)&g_bpe[np];
                bbv[r][0] = bv.x; bbv[r][1] = bv.y; bbv[r][2] = bv.z; bbv[r][3] = bv.w;
            }
        }
        wait_flags(g_flagG, qb, 4, s, tid);
        {
            const int par = s & 1;
#pragma unroll
            for (int r = 0; r < 2; ++r) {
                int id = bid * 512 + r * 256 + tid;
                int b = id & 63, j = id >> 6, np = 4 * j;
                float gate[4];
#pragma unroll
                for (int g = 0; g < 4; ++g) {
                    float sm = bbv[r][g] + gxa[r][g];
#pragma unroll
                    for (int z = 0; z < 4; ++z)
                        sm += g_partG[par][z][(size_t)(np + g) * 64 + b];
                    gate[g] = sm;
                }
                float c  = g_c[j * 64 + b];
                float cn = sigf(gate[1]) * c + sigf(gate[0]) * tanhf(gate[2]);
                float hn = sigf(gate[3]) * tanhf(cn);
                g_c[j * 64 + b] = cn;
                g_hB[s % 3][j * 64 + b] = hn;
                if (t == SS - 1) {
                    g_dec0[(1024 + j) * 64 + b] = hn;
                    g_dec0[j * 64 + b] = x[((size_t)b * SS + SS - 1) * 1024 + j];
                }
            }
        }
        __syncthreads();
        set_flag(g_flagC, bid, s, tid);
    }

    // resident decoder Whh slice (weights constant; no cross-CTA dependency)
    load_wres(Wres, g_WTdec + (size_t)(1024 + kz * 256) * 4096 + p * 128, tid);

    // ---------------- decoder (steps s = 513..1024) ----------------
    for (int t = 0; t < SS; ++t) {
        unsigned s = (unsigned)(SS + t + 1);
        int mprev = (t > 0) ? g_mask[t - 1] : 1;
        if (t == 0) {
            wait_flags(g_flagC, 0, 128, SS, tid);
            gemm_stream(g_dec0 + (size_t)(kz * 512) * 64,
                        g_WTdec + (size_t)(kz * 512) * 4096 + p * 128,
                        16, Ab, Wstr, g_partG[s & 1][kz] + (size_t)p * 128 * 64, tid);
        } else if (mprev) {
            wait_flags(g_flagC, kz * 32, 32, s - 1, tid);
            gemm_res(g_H + (size_t)(t - 1) * 65536 + (size_t)(kz * 256) * 64, Wres,
                     8, Ab, g_partG[s & 1][kz] + (size_t)p * 128 * 64, tid);
        } else {
            wait_flags(g_flagC, kz * 32, 32, s - 1, tid);
            gemm_stream(g_H + (size_t)(t - 1) * 65536 + (size_t)(kz * 256) * 64,
                        g_W0 + (size_t)(kz * 256) * 4096 + p * 128,
                        8, Ab, Wstr, g_partG[s & 1][kz] + (size_t)p * 128 * 64, tid);
        }
        set_flag(g_flagG, bid, s, tid);
        // prefetch tgtX/bias while waiting
        float gxa[2][4], bbv[2][4];
        {
            const float* txp = (t > 0 && mprev) ? (g_tgtX + (size_t)(t - 1) * 4096 * 64) : (const float*)0;
            const float* bb  = (t == 0 || mprev) ? g_bpd : g_bfu;
#pragma unroll
            for (int r = 0; r < 2; ++r) {
                int id = bid * 512 + r * 256 + tid;
                int b = id & 63, np = (id >> 6) * 4;
                if (txp) {
                    const float* gp = txp + (size_t)np * 64 + b;
                    gxa[r][0] = gp[0];   gxa[r][1] = gp[64];
                    gxa[r][2] = gp[128]; gxa[r][3] = gp[192];
                } else {
                    gxa[r][0] = 0.f; gxa[r][1] = 0.f; gxa[r][2] = 0.f; gxa[r][3] = 0.f;
                }
                float4 bv = *(const float4*)&bb[np];
                bbv[r][0] = bv.x; bbv[r][1] = bv.y; bbv[r][2] = bv.z; bbv[r][3] = bv.w;
            }
        }
        wait_flags(g_flagG, qb, 4, s, tid);
        {
            const int par = s & 1;
#pragma unroll
            for (int r = 0; r < 2; ++r) {
                int id = bid * 512 + r * 256 + tid;
                int b = id & 63, j = id >> 6, np = 4 * j;
                float gate[4];
#pragma unroll
                for (int g = 0; g < 4; ++g) {
                    float sm = bbv[r][g] + gxa[r][g];
#pragma unroll
                    for (int z = 0; z < 4; ++z)
                        sm += g_partG[par][z][(size_t)(np + g) * 64 + b];
                    gate[g] = sm;
                }
                float c  = g_c[j * 64 + b];
                float cn = sigf(gate[1]) * c + sigf(gate[0]) * tanhf(gate[2]);
                float hn = sigf(gate[3]) * tanhf(cn);
                g_c[j * 64 + b] = cn;
                g_H[(size_t)t * 65536 + j * 64 + b] = hn;
            }
        }
        __syncthreads();
        set_flag(g_flagC, bid, s, tid);
    }
}

// ============ shared 128x128 K=1024 accumulator (for big_pre) ============
__device__ __forceinline__ void mm128(const float* const rp[4], const float* __restrict__ Wb,
                                      float* As, float* Ws, ull acc[4][8], int tid)
{
    const int tyy = tid >> 4, tx = tid & 15, k4 = tid & 7;
#pragma unroll
    for (int s = 0; s < 4; ++s)
#pragma unroll
        for (int c = 0; c < 8; ++c) acc[s][c] = 0ull;

    float4 pa[4], pw[4];
#pragma unroll
    for (int i = 0; i < 4; ++i) {
        pa[i] = *(const float4*)(rp[i] + k4 * 4);
        int idx = tid + i * 256;
        pw[i] = *(const float4*)(Wb + (size_t)(idx >> 5) * 4096 + (idx & 31) * 4);
    }
    for (int kt = 0; kt < 32; ++kt) {
#pragma unroll
        for (int i = 0; i < 4; ++i) {
            int idx = tid + i * 256;
            int m = idx >> 3, cm = m >> 2;
            const float* e = (const float*)&pa[i];
#pragma unroll
            for (int r = 0; r < 4; ++r) {
                int k = k4 * 4 + r;
                As[k * 128 + ((cm ^ (k >> 2)) << 2) + (m & 3)] = e[r];
            }
            *(float4*)&Ws[(idx >> 5) * 128 + (idx & 31) * 4] = pw[i];
        }
        __syncthreads();
        if (kt + 1 < 32) {
            int kOff = (kt + 1) * 32;
#pragma unroll
            for (int i = 0; i < 4; ++i) {
                pa[i] = *(const float4*)(rp[i] + kOff + k4 * 4);
                int idx = tid + i * 256;
                pw[i] = *(const float4*)(Wb + (size_t)(kOff + (idx >> 5)) * 4096 + (idx & 31) * 4);
            }
        }
#pragma unroll
        for (int kk = 0; kk < 32; ++kk) {
            int sw = kk >> 2;
            ull a[4];
#pragma unroll
            for (int s = 0; s < 4; ++s) {
                int r = tyy + 16 * s;
                a[s] = *(const ull*)&As[kk * 128 + (((r >> 1) ^ sw) << 2) + 2 * (r & 1)];
            }
            float4 wA = *(const float4*)&Ws[kk * 128 + 8 * tx];
            float4 wB = *(const float4*)&Ws[kk * 128 + 8 * tx + 4];
            ull w[8];
            w[0] = dup2(wA.x); w[1] = dup2(wA.y); w[2] = dup2(wA.z); w[3] = dup2(wA.w);
            w[4] = dup2(wB.x); w[5] = dup2(wB.y); w[6] = dup2(wB.z); w[7] = dup2(wB.w);
#pragma unroll
            for (int s = 0; s < 4; ++s)
#pragma unroll
                for (int c = 0; c < 8; ++c)
                    fma2(acc[s][c], a[s], w[c]);
        }
        __syncthreads();
    }
}

// ============ big_pre: zy<256 gatesX, 256..511 tgtX, 512..519 W0, 520 b_fused ============
__global__ __launch_bounds__(256, 1)
void big_pre(const float* __restrict__ x, const float* __restrict__ target,
             const float* __restrict__ fc_b)
{
    __shared__ __align__(16) float As[32 * 128];
    __shared__ __align__(16) float Ws[32 * 128];
    const int tid = threadIdx.x;
    const int zy  = blockIdx.y;
    const int nBase = blockIdx.x * 128;

    if (zy == 520) {
        int np = blockIdx.x * 256 + tid;
        if (np < 4096) {
            float s = g_bpd[np];
            for (int n = 0; n < 1024; ++n)
                s += g_WTdec[(size_t)n * 4096 + np] * fc_b[n];
            g_bfu[np] = s;
        }
        return;
    }

    const int tyy = tid >> 4, tx = tid & 15;
    ull acc[4][8];
    const float* rp[4];

    if (zy < 512) {
        int z = zy >> 8, tp = zy & 255;
        if (z && !g_mask[2 * tp] && !g_mask[2 * tp + 1]) return;
        const float* src = z ? target : x;
#pragma unroll
        for (int i = 0; i < 4; ++i) {
            int idx = tid + i * 256;
            int mA = idx >> 3;
            rp[i] = src + ((size_t)(mA & 63) * SS + 2 * tp + (mA >> 6)) * 1024;
        }
        mm128(rp, (z ? g_WTdec : g_WTenc) + nBase, As, Ws, acc, tid);
        float* C = z ? g_tgtX : g_gatesX;
#pragma unroll
        for (int s = 0; s < 4; ++s) {
            int m = 2 * (tyy + 16 * s);
            int bb = m & 63, tsel = m >> 6;
            size_t tb = ((size_t)(2 * tp + tsel) * 4096 + nBase + 8 * tx) * 64 + bb;
#pragma unroll
            for (int c = 0; c < 8; ++c) {
                float2 v = unpack2(acc[s][c]);
                *(float2*)&C[tb + (size_t)c * 64] = v;
            }
        }
    } else {
        int mt = zy - 512;
#pragma unroll
        for (int i = 0; i < 4; ++i) {
            int idx = tid + i * 256;
            int mA = idx >> 3;
            rp[i] = g_WTfc + (size_t)(mt * 128 + mA) * 1024;
        }
        mm128(rp, g_WTdec + nBase, As, Ws, acc, tid);
#pragma unroll
        for (int s = 0; s < 4; ++s) {
            int m = 2 * (tyy + 16 * s);
            int j0 = mt * 128 + m;
#pragma unroll
            for (int c = 0; c < 8; ++c) {
                float2 v = unpack2(acc[s][c]);
                int col = nBase + 8 * tx + c;
                g_W0[(size_t)j0 * 4096 + col]       = v.x + g_WTdec[(size_t)(1024 + j0) * 4096 + col];
                g_W0[(size_t)(j0 + 1) * 4096 + col] = v.y + g_WTdec[(size_t)(1025 + j0) * 4096 + col];
            }
        }
    }
}

// ============ preds_out: out[b][t][:] = H[t][:,b] @ fcW^T + fc_b ============
__global__ __launch_bounds__(256, 1)
void preds_out(const float* __restrict__ fc_b, float* __restrict__ out)
{
    __shared__ __align__(16) float As[32 * 128];
    __shared__ __align__(16) float Ws[32 * 128];
    const int tid = threadIdx.x;
    const int nBase = blockIdx.x * 128;
    const int by = blockIdx.y;
    const int tyy = tid >> 4, tx = tid & 15;

    ull acc[4][8];
#pragma unroll
    for (int s = 0; s < 4; ++s)
#pragma unroll
        for (int c = 0; c < 8; ++c) acc[s][c] = 0ull;

    float4 pa[4], pw[4];
#pragma unroll
    for (int i = 0; i < 4; ++i) {
        int idx = tid + i * 256;
        int k = idx >> 5, c4 = idx & 31;
        pa[i] = *(const float4*)(g_H + (size_t)(2 * by + (c4 >> 4)) * 65536 + (size_t)k * 64 + ((c4 * 4) & 63));
        pw[i] = *(const float4*)(g_WTfc + (size_t)k * 1024 + nBase + c4 * 4);
    }
    for (int kt = 0; kt < 32; ++kt) {
#pragma unroll
        for (int i = 0; i < 4; ++i) {
            int idx = tid + i * 256;
            *(float4*)&As[(idx >> 5) * 128 + (idx & 31) * 4] = pa[i];
            *(float4*)&Ws[(idx >> 5) * 128 + (idx & 31) * 4] = pw[i];
        }
        __syncthreads();
        if (kt + 1 < 32) {
            int kOff = (kt + 1) * 32;
#pragma unroll
            for (int i = 0; i < 4; ++i) {
                int idx = tid + i * 256;
                int k = kOff + (idx >> 5), c4 = idx & 31;
                pa[i] = *(const float4*)(g_H + (size_t)(2 * by + (c4 >> 4)) * 65536 + (size_t)k * 64 + ((c4 * 4) & 63));
                pw[i] = *(const float4*)(g_WTfc + (size_t)k * 1024 + nBase + c4 * 4);
            }
        }
#pragma unroll
        for (int kk = 0; kk < 32; ++kk) {
            ull a[4];
#pragma unroll
            for (int s = 0; s < 4; ++s)
                a[s] = *(const ull*)&As[kk * 128 + 2 * (tyy + 16 * s)];
            float4 wA = *(const float4*)&Ws[kk * 128 + 8 * tx];
            float4 wB = *(const float4*)&Ws[kk * 128 + 8 * tx + 4];
            ull w[8];
            w[0] = dup2(wA.x); w[1] = dup2(wA.y); w[2] = dup2(wA.z); w[3] = dup2(wA.w);
            w[4] = dup2(wB.x); w[5] = dup2(wB.y); w[6] = dup2(wB.z); w[7] = dup2(wB.w);
#pragma unroll
            for (int s = 0; s < 4; ++s)
#pragma unroll
                for (int c = 0; c < 8; ++c)
                    fma2(acc[s][c], a[s], w[c]);
        }
        __syncthreads();
    }
    float fcb[8];
#pragma unroll
    for (int c = 0; c < 8; ++c) fcb[c] = fc_b[nBase + 8 * tx + c];
#pragma unroll
    for (int s = 0; s < 4; ++s) {
        int m = 2 * (tyy + 16 * s);
        int t0 = 2 * by + (m >> 6);
        int b0 = m & 63;
        size_t o0 = ((size_t)b0 * SS + t0) * 1024 + nBase + 8 * tx;
        size_t o1 = ((size_t)(b0 + 1) * SS + t0) * 1024 + nBase + 8 * tx;
#pragma unroll
        for (int c = 0; c < 8; c += 2) {
            float2 va = unpack2(acc[s][c]);
            float2 vb = unpack2(acc[s][c + 1]);
            *(float2*)&out[o0 + c] = make_float2(va.x + fcb[c], vb.x + fcb[c + 1]);
            *(float2*)&out[o1 + c] = make_float2(va.y + fcb[c], vb.y + fcb[c + 1]);
        }
    }
}

// ---- fused weight transposes ----
__global__ void tposeAll(const float* __restrict__ eWih, const float* __restrict__ eWhh,
                         const float* __restrict__ dWih, const float* __restrict__ dWhh,
                         const float* __restrict__ fcW)
{
    __shared__ float t[32][33];
    int z = blockIdx.z;
    int k0 = blockIdx.x * 32, n0 = blockIdx.y * 32;
    if (z == 4) {
        if (blockIdx.y >= 32) return;
#pragma unroll
        for (int i = 0; i < 32; i += 8)
            t[threadIdx.y + i][threadIdx.x] = fcW[(size_t)(n0 + threadIdx.y + i) * 1024 + k0 + threadIdx.x];
        __syncthreads();
#pragma unroll
        for (int i = 0; i < 32; i += 8)
            g_WTfc[(size_t)(k0 + threadIdx.y + i) * 1024 + n0 + threadIdx.x] = t[threadIdx.x][threadIdx.y + i];
        return;
    }
    const float* src = (z == 0) ? eWih : (z == 1) ? eWhh : (z == 2) ? dWih : dWhh;
    float* dst = ((z < 2) ? g_WTenc : g_WTdec) + (size_t)(z & 1) * 1024 * 4096;
#pragma unroll
    for (int i = 0; i < 32; i += 8) {
        int np = n0 + threadIdx.y + i;
        int row = ((np & 3) << 10) + (np >> 2);
        t[threadIdx.y + i][threadIdx.x] = src[(size_t)row * 1024 + k0 + threadIdx.x];
    }
    __syncthreads();
#pragma unroll
    for (int i = 0; i < 32; i += 8)
        dst[(size_t)(k0 + threadIdx.y + i) * 4096 + n0 + threadIdx.x] = t[threadIdx.x][threadIdx.y + i];
}

// ---------------- init + mask decode ----------------
__global__ void mask_init(const unsigned char* __restrict__ p,
                          const float* __restrict__ enc_b, const float* __restrict__ dec_b)
{
    int tid = threadIdx.x;
    int i = blockIdx.x * 512 + tid;
    g_c[i] = 0.0f;
    g_hB[0][i] = 0.0f;
    if (i < 4096) {
        int row = ((i & 3) << 10) + (i >> 2);
        g_bpe[i] = enc_b[row];
        g_bpd[i] = dec_b[row];
    }
    if (blockIdx.x == 2) {
#pragma unroll
        for (int k = 0; k < 8; ++k) g_flagG[tid + 512 * k] = 0u;
    }
    if (blockIdx.x == 3) {
#pragma unroll
        for (int k = 0; k < 8; ++k) g_flagC[tid + 512 * k] = 0u;
    }
    if (blockIdx.x == 0) {
        __shared__ int s_odd, s_big;
        if (tid == 0) { s_odd = 0; s_big = 0; }
        __syncthreads();
        unsigned char v = p[tid];
        if ((tid & 3) && v)  atomicOr(&s_odd, 1);
        if (v > 1)           atomicOr(&s_big, 1);
        __syncthreads();
        int m;
        if (s_big)        m = (((const float*)p)[tid] != 0.0f);
        else if (s_odd)   m = (p[tid] != 0);
        else              m = (((const int*)p)[tid] != 0);
        g_mask[tid] = m;
    }
}

// ---------------- host ----------------
extern "C" void kernel_launch(void* const* d_in, const int* in_sizes, int n_in,
                              void* d_out, int out_size)
{
    (void)in_sizes; (void)n_in; (void)out_size;
    const float* x       = (const float*)d_in[0];
    const float* target  = (const float*)d_in[1];
    const float* enc_Wih = (const float*)d_in[2];
    const float* enc_Whh = (const float*)d_in[3];
    const float* enc_b   = (const float*)d_in[4];
    const float* dec_Wih = (const float*)d_in[5];
    const float* dec_Whh = (const float*)d_in[6];
    const float* dec_b   = (const float*)d_in[7];
    const float* fc_W    = (const float*)d_in[8];
    const float* fc_b    = (const float*)d_in[9];
    const unsigned char* tf_mask = (const unsigned char*)d_in[10];
    float* out = (float*)d_out;

    static int smem_set = 0;
    if (!smem_set) {
        cudaFuncSetAttribute(seq2seq_persist,
                             cudaFuncAttributeMaxDynamicSharedMemorySize, SMEM_BYTES);
        smem_set = 1;
    }

    // #1: init + mask decode (+ flag reset)
    mask_init<<<128, 512>>>(tf_mask, enc_b, dec_b);
    // #2: weight transposes
    tposeAll<<<dim3(32, 128, 5), dim3(32, 8)>>>(enc_Wih, enc_Whh, dec_Wih, dec_Whh, fc_W);
    // #3: gatesX + tgtX + W0 + b_fused
    big_pre<<<dim3(32, 521), 256>>>(x, target, fc_b);
    // #4 (profiled): persistent recurrence with resident weights
    seq2seq_persist<<<NBLK, 256, SMEM_BYTES>>>(x);
    // #5: all predictions post-hoc
    preds_out<<<dim3(8, 256), 256>>>(fc_b, out);
}

// round 16
// speedup vs baseline: 1.1865x; 1.0387x over previous
#include <cuda_runtime.h>
#include <math.h>
#include <stdint.h>

typedef unsigned long long ull;

#define SS 512
#define NBLK 128
// dyn smem floats: [0,32768) resident W, [32768,36864) A dbuf, [36864,45056) W stream dbuf
#define SMEM_FLOATS 45056
#define SMEM_BYTES  (SMEM_FLOATS * 4)

// ---------------- device scratch ----------------
__device__ float g_WTenc[2048 * 4096];   // [k][n'=4j+g]; rows 0..1023 Wih^T, 1024..2047 Whh^T
__device__ float g_WTdec[2048 * 4096];
__device__ float g_WTfc [1024 * 1024];
__device__ float g_W0   [1024 * 4096];
__device__ float g_gatesX[(size_t)512 * 1024 * 256]; // [t][j][b][g]  (vec4 gates)
__device__ float g_tgtX  [(size_t)512 * 1024 * 256]; // [t][j][b][g]
__device__ float g_H     [(size_t)512 * 1024 * 64];  // [t][j][b]
__device__ float g_hB  [3][1024 * 64];
__device__ float g_dec0[2048 * 64];
__device__ float g_c   [1024 * 64];
__device__ float g_partG[2][4][1024 * 256];          // [par][kz][j][b][g]
__device__ float g_bpe[4096], g_bpd[4096], g_bfu[4096];
__device__ int   g_mask[512];
__device__ unsigned g_flagG[128 * 32];
__device__ unsigned g_flagC[128 * 32];

// ---------------- f32x2 helpers ----------------
__device__ __forceinline__ ull dup2(float v) {
    ull r; unsigned u = __float_as_uint(v);
    asm("mov.b64 %0, {%1, %1};" : "=l"(r) : "r"(u));
    return r;
}
__device__ __forceinline__ void fma2(ull& acc, ull a, ull b) {
    asm("fma.rn.f32x2 %0, %1, %2, %0;" : "+l"(acc) : "l"(a), "l"(b));
}
__device__ __forceinline__ float2 unpack2(ull v) {
    unsigned lo, hi;
    asm("mov.b64 {%0, %1}, %2;" : "=r"(lo), "=r"(hi) : "l"(v));
    return make_float2(__uint_as_float(lo), __uint_as_float(hi));
}
__device__ __forceinline__ float sigf(float x) { return 1.0f / (1.0f + expf(-x)); }

// ---------------- flag sync ----------------
__device__ __forceinline__ void wait_flags(const unsigned* f, int base, int cnt,
                                           unsigned s, int tid)
{
    if (tid < cnt) {
        const volatile unsigned* p = (const volatile unsigned*)(f + (size_t)(base + tid) * 32);
        while (*p < s) { }
        __threadfence();
    }
    __syncthreads();
}
__device__ __forceinline__ void set_flag(unsigned* f, int bid, unsigned s, int tid)
{
    if (tid == 0) {
        __threadfence();
        *(volatile unsigned*)(f + (size_t)bid * 32) = s;
    }
}

// ---- vec4 partial store epilogue: dst = g_partG[par][kz] + p*32*256 ----
__device__ __forceinline__ void store_part(float* __restrict__ dst, ull acc[4][4],
                                           int ty, int tx)
{
#pragma unroll
    for (int q = 0; q < 4; ++q) {
        float2 v0 = unpack2(acc[q][0]);
        float2 v1 = unpack2(acc[q][1]);
        float2 v2 = unpack2(acc[q][2]);
        float2 v3 = unpack2(acc[q][3]);
        int b = 8 * ty + 2 * q;
        *(float4*)&dst[tx * 256 + b * 4]       = make_float4(v0.x, v1.x, v2.x, v3.x);
        *(float4*)&dst[tx * 256 + (b + 1) * 4] = make_float4(v0.y, v1.y, v2.y, v3.y);
    }
}

// ============ resident-W gate GEMM: 64b x 128n tile, 1 sync/kt ============
__device__ __forceinline__ void gemm_res(const float* __restrict__ A,
                                         const float* __restrict__ Wres,
                                         int nKT, float* Ab,
                                         float* __restrict__ dst, int tid)
{
    const int ty = tid >> 5, tx = tid & 31;
    ull acc[4][4];
#pragma unroll
    for (int q = 0; q < 4; ++q)
#pragma unroll
        for (int c = 0; c < 4; ++c) acc[q][c] = 0ull;

    float4 pa[2];
#pragma unroll
    for (int i = 0; i < 2; ++i) {
        int idx = tid + i * 256;
        pa[i] = *(const float4*)(A + (size_t)(idx >> 4) * 64 + (idx & 15) * 4);
    }
#pragma unroll
    for (int i = 0; i < 2; ++i) {
        int idx = tid + i * 256;
        *(float4*)&Ab[(idx >> 4) * 64 + (idx & 15) * 4] = pa[i];
    }
    __syncthreads();

    for (int kt = 0; kt < nKT; ++kt) {
        const int cb = kt & 1;
        const float* Ac = Ab + cb * 2048;
        const float* Wk = Wres + kt * (32 * 128);
        const bool more = (kt + 1 < nKT);
        if (more) {
            int kOff = (kt + 1) * 32;
#pragma unroll
            for (int i = 0; i < 2; ++i) {
                int idx = tid + i * 256;
                pa[i] = *(const float4*)(A + (size_t)(kOff + (idx >> 4)) * 64 + (idx & 15) * 4);
            }
        }
#pragma unroll
        for (int kk = 0; kk < 32; ++kk) {
            ulonglong2 aa = *(const ulonglong2*)&Ac[kk * 64 + 8 * ty];
            ulonglong2 ab = *(const ulonglong2*)&Ac[kk * 64 + 8 * ty + 4];
            float4 wv = *(const float4*)&Wk[kk * 128 + 4 * tx];
            ull w0 = dup2(wv.x), w1 = dup2(wv.y), w2 = dup2(wv.z), w3 = dup2(wv.w);
            fma2(acc[0][0], aa.x, w0); fma2(acc[0][1], aa.x, w1);
            fma2(acc[0][2], aa.x, w2); fma2(acc[0][3], aa.x, w3);
            fma2(acc[1][0], aa.y, w0); fma2(acc[1][1], aa.y, w1);
            fma2(acc[1][2], aa.y, w2); fma2(acc[1][3], aa.y, w3);
            fma2(acc[2][0], ab.x, w0); fma2(acc[2][1], ab.x, w1);
            fma2(acc[2][2], ab.x, w2); fma2(acc[2][3], ab.x, w3);
            fma2(acc[3][0], ab.y, w0); fma2(acc[3][1], ab.y, w1);
            fma2(acc[3][2], ab.y, w2); fma2(acc[3][3], ab.y, w3);
        }
        if (more) {
            float* An = Ab + (cb ^ 1) * 2048;
#pragma unroll
            for (int i = 0; i < 2; ++i) {
                int idx = tid + i * 256;
                *(float4*)&An[(idx >> 4) * 64 + (idx & 15) * 4] = pa[i];
            }
        }
        __syncthreads();
    }
    store_part(dst, acc, ty, tx);
}

// ============ streamed gate GEMM: double-buffered A and W, 1 sync/kt ============
__device__ __forceinline__ void gemm_stream(const float* __restrict__ A,
                                            const float* __restrict__ Wp,
                                            int nKT, float* Ab, float* Wb,
                                            float* __restrict__ dst, int tid)
{
    const int ty = tid >> 5, tx = tid & 31;
    ull acc[4][4];
#pragma unroll
    for (int q = 0; q < 4; ++q)
#pragma unroll
        for (int c = 0; c < 4; ++c) acc[q][c] = 0ull;

    float4 pa[2], pw[4];
#pragma unroll
    for (int i = 0; i < 2; ++i) {
        int idx = tid + i * 256;
        pa[i] = *(const float4*)(A + (size_t)(idx >> 4) * 64 + (idx & 15) * 4);
    }
#pragma unroll
    for (int i = 0; i < 4; ++i) {
        int idx = tid + i * 256;
        pw[i] = *(const float4*)(Wp + (size_t)(idx >> 5) * 4096 + (idx & 31) * 4);
    }
#pragma unroll
    for (int i = 0; i < 2; ++i) {
        int idx = tid + i * 256;
        *(float4*)&Ab[(idx >> 4) * 64 + (idx & 15) * 4] = pa[i];
    }
#pragma unroll
    for (int i = 0; i < 4; ++i) {
        int idx = tid + i * 256;
        *(float4*)&Wb[(idx >> 5) * 128 + (idx & 31) * 4] = pw[i];
    }
    __syncthreads();

    for (int kt = 0; kt < nKT; ++kt) {
        const int cb = kt & 1;
        const float* Ac = Ab + cb * 2048;
        const float* Wc = Wb + cb * 4096;
        const bool more = (kt + 1 < nKT);
        if (more) {
            int kOff = (kt + 1) * 32;
#pragma unroll
            for (int i = 0; i < 2; ++i) {
                int idx = tid + i * 256;
                pa[i] = *(const float4*)(A + (size_t)(kOff + (idx >> 4)) * 64 + (idx & 15) * 4);
            }
#pragma unroll
            for (int i = 0; i < 4; ++i) {
                int idx = tid + i * 256;
                pw[i] = *(const float4*)(Wp + (size_t)(kOff + (idx >> 5)) * 4096 + (idx & 31) * 4);
            }
        }
#pragma unroll
        for (int kk = 0; kk < 32; ++kk) {
            ulonglong2 aa = *(const ulonglong2*)&Ac[kk * 64 + 8 * ty];
            ulonglong2 ab = *(const ulonglong2*)&Ac[kk * 64 + 8 * ty + 4];
            float4 wv = *(const float4*)&Wc[kk * 128 + 4 * tx];
            ull w0 = dup2(wv.x), w1 = dup2(wv.y), w2 = dup2(wv.z), w3 = dup2(wv.w);
            fma2(acc[0][0], aa.x, w0); fma2(acc[0][1], aa.x, w1);
            fma2(acc[0][2], aa.x, w2); fma2(acc[0][3], aa.x, w3);
            fma2(acc[1][0], aa.y, w0); fma2(acc[1][1], aa.y, w1);
            fma2(acc[1][2], aa.y, w2); fma2(acc[1][3], aa.y, w3);
            fma2(acc[2][0], ab.x, w0); fma2(acc[2][1], ab.x, w1);
            fma2(acc[2][2], ab.x, w2); fma2(acc[2][3], ab.x, w3);
            fma2(acc[3][0], ab.y, w0); fma2(acc[3][1], ab.y, w1);
            fma2(acc[3][2], ab.y, w2); fma2(acc[3][3], ab.y, w3);
        }
        if (more) {
            float* An = Ab + (cb ^ 1) * 2048;
            float* Wn = Wb + (cb ^ 1) * 4096;
#pragma unroll
            for (int i = 0; i < 2; ++i) {
                int idx = tid + i * 256;
                *(float4*)&An[(idx >> 4) * 64 + (idx & 15) * 4] = pa[i];
            }
#pragma unroll
            for (int i = 0; i < 4; ++i) {
                int idx = tid + i * 256;
                *(float4*)&Wn[(idx >> 5) * 128 + (idx & 31) * 4] = pw[i];
            }
        }
        __syncthreads();
    }
    store_part(dst, acc, ty, tx);
}

__device__ __forceinline__ void load_wres(float* Wres, const float* __restrict__ Wsrc, int tid)
{
    for (int r = tid; r < 8192; r += 256)
        ((float4*)Wres)[r] = *(const float4*)(Wsrc + (size_t)(r >> 5) * 4096 + (r & 31) * 4);
    __syncthreads();
}

// ============ persistent kernel: 128 CTAs x 256 threads ============
__global__ __launch_bounds__(256, 1)
void seq2seq_persist(const float* __restrict__ x)
{
    extern __shared__ __align__(16) float smem[];
    float* Wres = smem;
    float* Ab   = smem + 32768;
    float* Wstr = smem + 36864;

    const int tid = threadIdx.x;
    const int bid = blockIdx.x;
    const int p   = bid >> 2;
    const int kz  = bid & 3;
    const int qb  = (bid >> 2) * 4;

    load_wres(Wres, g_WTenc + (size_t)(1024 + kz * 256) * 4096 + p * 128, tid);

    // ---------------- encoder ----------------
    for (int t = 0; t < SS; ++t) {
        unsigned s = (unsigned)(t + 1);
        wait_flags(g_flagC, kz * 32, 32, s - 1, tid);
        gemm_res(g_hB[(s - 1) % 3] + (size_t)(kz * 256) * 64, Wres,
                 8, Ab, g_partG[s & 1][kz] + (size_t)p * 32 * 256, tid);
        set_flag(g_flagG, bid, s, tid);
        float4 gxa[2], bbv[2];
        {
#pragma unroll
            for (int r = 0; r < 2; ++r) {
                int id = bid * 512 + r * 256 + tid;
                int b = id & 63, j = id >> 6;
                gxa[r] = *(const float4*)&g_gatesX[((size_t)t * 1024 + j) * 256 + b * 4];
                bbv[r] = *(const float4*)&g_bpe[4 * j];
            }
        }
        wait_flags(g_flagG, qb, 4, s, tid);
        {
            const int par = s & 1;
#pragma unroll
            for (int r = 0; r < 2; ++r) {
                int id = bid * 512 + r * 256 + tid;
                int b = id & 63, j = id >> 6;
                size_t po = (size_t)j * 256 + b * 4;
                float4 p0 = *(const float4*)&g_partG[par][0][po];
                float4 p1 = *(const float4*)&g_partG[par][1][po];
                float4 p2 = *(const float4*)&g_partG[par][2][po];
                float4 p3 = *(const float4*)&g_partG[par][3][po];
                float gi = bbv[r].x + gxa[r].x + p0.x + p1.x + p2.x + p3.x;
                float gf = bbv[r].y + gxa[r].y + p0.y + p1.y + p2.y + p3.y;
                float gg = bbv[r].z + gxa[r].z + p0.z + p1.z + p2.z + p3.z;
                float go = bbv[r].w + gxa[r].w + p0.w + p1.w + p2.w + p3.w;
                float c  = g_c[j * 64 + b];
                float cn = sigf(gf) * c + sigf(gi) * tanhf(gg);
                float hn = sigf(go) * tanhf(cn);
                g_c[j * 64 + b] = cn;
                g_hB[s % 3][j * 64 + b] = hn;
                if (t == SS - 1) {
                    g_dec0[(1024 + j) * 64 + b] = hn;
                    g_dec0[j * 64 + b] = x[((size_t)b * SS + SS - 1) * 1024 + j];
                }
            }
        }
        __syncthreads();
        set_flag(g_flagC, bid, s, tid);
    }

    load_wres(Wres, g_WTdec + (size_t)(1024 + kz * 256) * 4096 + p * 128, tid);

    // ---------------- decoder ----------------
    for (int t = 0; t < SS; ++t) {
        unsigned s = (unsigned)(SS + t + 1);
        int mprev = (t > 0) ? g_mask[t - 1] : 1;
        if (t == 0) {
            wait_flags(g_flagC, 0, 128, SS, tid);
            gemm_stream(g_dec0 + (size_t)(kz * 512) * 64,
                        g_WTdec + (size_t)(kz * 512) * 4096 + p * 128,
                        16, Ab, Wstr, g_partG[s & 1][kz] + (size_t)p * 32 * 256, tid);
        } else if (mprev) {
            wait_flags(g_flagC, kz * 32, 32, s - 1, tid);
            gemm_res(g_H + (size_t)(t - 1) * 65536 + (size_t)(kz * 256) * 64, Wres,
                     8, Ab, g_partG[s & 1][kz] + (size_t)p * 32 * 256, tid);
        } else {
            wait_flags(g_flagC, kz * 32, 32, s - 1, tid);
            gemm_stream(g_H + (size_t)(t - 1) * 65536 + (size_t)(kz * 256) * 64,
                        g_W0 + (size_t)(kz * 256) * 4096 + p * 128,
                        8, Ab, Wstr, g_partG[s & 1][kz] + (size_t)p * 32 * 256, tid);
        }
        set_flag(g_flagG, bid, s, tid);
        float4 gxa[2], bbv[2];
        {
            const int useT = (t > 0 && mprev);
            const float* bb = (t == 0 || mprev) ? g_bpd : g_bfu;
#pragma unroll
            for (int r = 0; r < 2; ++r) {
                int id = bid * 512 + r * 256 + tid;
                int b = id & 63, j = id >> 6;
                gxa[r] = useT ? *(const float4*)&g_tgtX[((size_t)(t - 1) * 1024 + j) * 256 + b * 4]
                              : make_float4(0.f, 0.f, 0.f, 0.f);
                bbv[r] = *(const float4*)&bb[4 * j];
            }
        }
        wait_flags(g_flagG, qb, 4, s, tid);
        {
            const int par = s & 1;
#pragma unroll
            for (int r = 0; r < 2; ++r) {
                int id = bid * 512 + r * 256 + tid;
                int b = id & 63, j = id >> 6;
                size_t po = (size_t)j * 256 + b * 4;
                float4 p0 = *(const float4*)&g_partG[par][0][po];
                float4 p1 = *(const float4*)&g_partG[par][1][po];
                float4 p2 = *(const float4*)&g_partG[par][2][po];
                float4 p3 = *(const float4*)&g_partG[par][3][po];
                float gi = bbv[r].x + gxa[r].x + p0.x + p1.x + p2.x + p3.x;
                float gf = bbv[r].y + gxa[r].y + p0.y + p1.y + p2.y + p3.y;
                float gg = bbv[r].z + gxa[r].z + p0.z + p1.z + p2.z + p3.z;
                float go = bbv[r].w + gxa[r].w + p0.w + p1.w + p2.w + p3.w;
                float c  = g_c[j * 64 + b];
                float cn = sigf(gf) * c + sigf(gi) * tanhf(gg);
                float hn = sigf(go) * tanhf(cn);
                g_c[j * 64 + b] = cn;
                g_H[(size_t)t * 65536 + j * 64 + b] = hn;
            }
        }
        __syncthreads();
        set_flag(g_flagC, bid, s, tid);
    }
}

// ============ mm128: 128x128 K=1024 fp32 accumulator ============
__device__ __forceinline__ void mm128(const float* const rp[4], const float* __restrict__ Wb,
                                      float* As, float* Ws, ull acc[4][8], int tid)
{
    const int tyy = tid >> 4, tx = tid & 15, k4 = tid & 7;
#pragma unroll
    for (int s = 0; s < 4; ++s)
#pragma unroll
        for (int c = 0; c < 8; ++c) acc[s][c] = 0ull;

    float4 pa[4], pw[4];
#pragma unroll
    for (int i = 0; i < 4; ++i) {
        pa[i] = *(const float4*)(rp[i] + k4 * 4);
        int idx = tid + i * 256;
        pw[i] = *(const float4*)(Wb + (size_t)(idx >> 5) * 4096 + (idx & 31) * 4);
    }
    for (int kt = 0; kt < 32; ++kt) {
#pragma unroll
        for (int i = 0; i < 4; ++i) {
            int idx = tid + i * 256;
            int m = idx >> 3, cm = m >> 2;
            const float* e = (const float*)&pa[i];
#pragma unroll
            for (int r = 0; r < 4; ++r) {
                int k = k4 * 4 + r;
                As[k * 128 + ((cm ^ (k >> 2)) << 2) + (m & 3)] = e[r];
            }
            *(float4*)&Ws[(idx >> 5) * 128 + (idx & 31) * 4] = pw[i];
        }
        __syncthreads();
        if (kt + 1 < 32) {
            int kOff = (kt + 1) * 32;
#pragma unroll
            for (int i = 0; i < 4; ++i) {
                pa[i] = *(const float4*)(rp[i] + kOff + k4 * 4);
                int idx = tid + i * 256;
                pw[i] = *(const float4*)(Wb + (size_t)(kOff + (idx >> 5)) * 4096 + (idx & 31) * 4);
            }
        }
#pragma unroll
        for (int kk = 0; kk < 32; ++kk) {
            int sw = kk >> 2;
            ull a[4];
#pragma unroll
            for (int s = 0; s < 4; ++s) {
                int r = tyy + 16 * s;
                a[s] = *(const ull*)&As[kk * 128 + (((r >> 1) ^ sw) << 2) + 2 * (r & 1)];
            }
            float4 wA = *(const float4*)&Ws[kk * 128 + 8 * tx];
            float4 wB = *(const float4*)&Ws[kk * 128 + 8 * tx + 4];
            ull w[8];
            w[0] = dup2(wA.x); w[1] = dup2(wA.y); w[2] = dup2(wA.z); w[3] = dup2(wA.w);
            w[4] = dup2(wB.x); w[5] = dup2(wB.y); w[6] = dup2(wB.z); w[7] = dup2(wB.w);
#pragma unroll
            for (int s = 0; s < 4; ++s)
#pragma unroll
                for (int c = 0; c < 8; ++c)
                    fma2(acc[s][c], a[s], w[c]);
        }
        __syncthreads();
    }
}

// ============ big_pre: zy<256 gatesX, 256..511 tgtX, 512..519 W0, 520 b_fused ============
__global__ __launch_bounds__(256, 1)
void big_pre(const float* __restrict__ x, const float* __restrict__ target,
             const float* __restrict__ fc_b)
{
    __shared__ __align__(16) float As[32 * 128];
    __shared__ __align__(16) float Ws[32 * 128];
    const int tid = threadIdx.x;
    const int zy  = blockIdx.y;
    const int nBase = blockIdx.x * 128;

    if (zy == 520) {
        int np = blockIdx.x * 256 + tid;
        if (np < 4096) {
            float s = g_bpd[np];
            for (int n = 0; n < 1024; ++n)
                s += g_WTdec[(size_t)n * 4096 + np] * fc_b[n];
            g_bfu[np] = s;
        }
        return;
    }

    const int tyy = tid >> 4, tx = tid & 15;
    ull acc[4][8];
    const float* rp[4];

    if (zy < 512) {
        int z = zy >> 8, tp = zy & 255;
        if (z && !g_mask[2 * tp] && !g_mask[2 * tp + 1]) return;
        const float* src = z ? target : x;
#pragma unroll
        for (int i = 0; i < 4; ++i) {
            int idx = tid + i * 256;
            int mA = idx >> 3;
            rp[i] = src + ((size_t)(mA & 63) * SS + 2 * tp + (mA >> 6)) * 1024;
        }
        mm128(rp, (z ? g_WTdec : g_WTenc) + nBase, As, Ws, acc, tid);
        float* C = z ? g_tgtX : g_gatesX;
        const int j0 = (nBase >> 2) + 2 * tx;
#pragma unroll
        for (int s = 0; s < 4; ++s) {
            int m = 2 * (tyy + 16 * s);
            int bb = m & 63, tsel = m >> 6;
            int t0 = 2 * tp + tsel;
            float2 px[8];
#pragma unroll
            for (int c = 0; c < 8; ++c) px[c] = unpack2(acc[s][c]);
            size_t base = ((size_t)t0 * 1024 + j0) * 256 + bb * 4;
            *(float4*)&C[base]           = make_float4(px[0].x, px[1].x, px[2].x, px[3].x);
            *(float4*)&C[base + 4]       = make_float4(px[0].y, px[1].y, px[2].y, px[3].y);
            *(float4*)&C[base + 256]     = make_float4(px[4].x, px[5].x, px[6].x, px[7].x);
            *(float4*)&C[base + 256 + 4] = make_float4(px[4].y, px[5].y, px[6].y, px[7].y);
        }
    } else {
        int mt = zy - 512;
#pragma unroll
        for (int i = 0; i < 4; ++i) {
            int idx = tid + i * 256;
            int mA = idx >> 3;
            rp[i] = g_WTfc + (size_t)(mt * 128 + mA) * 1024;
        }
        mm128(rp, g_WTdec + nBase, As, Ws, acc, tid);
#pragma unroll
        for (int s = 0; s < 4; ++s) {
            int m = 2 * (tyy + 16 * s);
            int j0 = mt * 128 + m;
#pragma unroll
            for (int c = 0; c < 8; ++c) {
                float2 v = unpack2(acc[s][c]);
                int col = nBase + 8 * tx + c;
                g_W0[(size_t)j0 * 4096 + col]       = v.x + g_WTdec[(size_t)(1024 + j0) * 4096 + col];
                g_W0[(size_t)(j0 + 1) * 4096 + col] = v.y + g_WTdec[(size_t)(1025 + j0) * 4096 + col];
            }
        }
    }
}

// ============ preds_out: out[b][t][:] = H[t][:,b] @ fcW^T + fc_b ============
__global__ __launch_bounds__(256, 1)
void preds_out(const float* __restrict__ fc_b, float* __restrict__ out)
{
    __shared__ __align__(16) float As[32 * 128];
    __shared__ __align__(16) float Ws[32 * 128];
    const int tid = threadIdx.x;
    const int nBase = blockIdx.x * 128;
    const int by = blockIdx.y;
    const int tyy = tid >> 4, tx = tid & 15;

    ull acc[4][8];
#pragma unroll
    for (int s = 0; s < 4; ++s)
#pragma unroll
        for (int c = 0; c < 8; ++c) acc[s][c] = 0ull;

    float4 pa[4], pw[4];
#pragma unroll
    for (int i = 0; i < 4; ++i) {
        int idx = tid + i * 256;
        int k = idx >> 5, c4 = idx & 31;
        pa[i] = *(const float4*)(g_H + (size_t)(2 * by + (c4 >> 4)) * 65536 + (size_t)k * 64 + ((c4 * 4) & 63));
        pw[i] = *(const float4*)(g_WTfc + (size_t)k * 1024 + nBase + c4 * 4);
    }
    for (int kt = 0; kt < 32; ++kt) {
#pragma unroll
        for (int i = 0; i < 4; ++i) {
            int idx = tid + i * 256;
            *(float4*)&As[(idx >> 5) * 128 + (idx & 31) * 4] = pa[i];
            *(float4*)&Ws[(idx >> 5) * 128 + (idx & 31) * 4] = pw[i];
        }
        __syncthreads();
        if (kt + 1 < 32) {
            int kOff = (kt + 1) * 32;
#pragma unroll
            for (int i = 0; i < 4; ++i) {
                int idx = tid + i * 256;
                int k = kOff + (idx >> 5), c4 = idx & 31;
                pa[i] = *(const float4*)(g_H + (size_t)(2 * by + (c4 >> 4)) * 65536 + (size_t)k * 64 + ((c4 * 4) & 63));
                pw[i] = *(const float4*)(g_WTfc + (size_t)k * 1024 + nBase + c4 * 4);
            }
        }
#pragma unroll
        for (int kk = 0; kk < 32; ++kk) {
            ull a[4];
#pragma unroll
            for (int s = 0; s < 4; ++s)
                a[s] = *(const ull*)&As[kk * 128 + 2 * (tyy + 16 * s)];
            float4 wA = *(const float4*)&Ws[kk * 128 + 8 * tx];
            float4 wB = *(const float4*)&Ws[kk * 128 + 8 * tx + 4];
            ull w[8];
            w[0] = dup2(wA.x); w[1] = dup2(wA.y); w[2] = dup2(wA.z); w[3] = dup2(wA.w);
            w[4] = dup2(wB.x); w[5] = dup2(wB.y); w[6] = dup2(wB.z); w[7] = dup2(wB.w);
#pragma unroll
            for (int s = 0; s < 4; ++s)
#pragma unroll
                for (int c = 0; c < 8; ++c)
                    fma2(acc[s][c], a[s], w[c]);
        }
        __syncthreads();
    }
    float fcb[8];
#pragma unroll
    for (int c = 0; c < 8; ++c) fcb[c] = fc_b[nBase + 8 * tx + c];
#pragma unroll
    for (int s = 0; s < 4; ++s) {
        int m = 2 * (tyy + 16 * s);
        int t0 = 2 * by + (m >> 6);
        int b0 = m & 63;
        size_t o0 = ((size_t)b0 * SS + t0) * 1024 + nBase + 8 * tx;
        size_t o1 = ((size_t)(b0 + 1) * SS + t0) * 1024 + nBase + 8 * tx;
#pragma unroll
        for (int c = 0; c < 8; c += 2) {
            float2 va = unpack2(acc[s][c]);
            float2 vb = unpack2(acc[s][c + 1]);
            *(float2*)&out[o0 + c] = make_float2(va.x + fcb[c], vb.x + fcb[c + 1]);
            *(float2*)&out[o1 + c] = make_float2(va.y + fcb[c], vb.y + fcb[c + 1]);
        }
    }
}

// ---- fused weight transposes ----
__global__ void tposeAll(const float* __restrict__ eWih, const float* __restrict__ eWhh,
                         const float* __restrict__ dWih, const float* __restrict__ dWhh,
                         const float* __restrict__ fcW)
{
    __shared__ float t[32][33];
    int z = blockIdx.z;
    int k0 = blockIdx.x * 32, n0 = blockIdx.y * 32;
    if (z == 4) {
        if (blockIdx.y >= 32) return;
#pragma unroll
        for (int i = 0; i < 32; i += 8)
            t[threadIdx.y + i][threadIdx.x] = fcW[(size_t)(n0 + threadIdx.y + i) * 1024 + k0 + threadIdx.x];
        __syncthreads();
#pragma unroll
        for (int i = 0; i < 32; i += 8)
            g_WTfc[(size_t)(k0 + threadIdx.y + i) * 1024 + n0 + threadIdx.x] = t[threadIdx.x][threadIdx.y + i];
        return;
    }
    const float* src = (z == 0) ? eWih : (z == 1) ? eWhh : (z == 2) ? dWih : dWhh;
    float* dst = ((z < 2) ? g_WTenc : g_WTdec) + (size_t)(z & 1) * 1024 * 4096;
#pragma unroll
    for (int i = 0; i < 32; i += 8) {
        int np = n0 + threadIdx.y + i;
        int row = ((np & 3) << 10) + (np >> 2);
        t[threadIdx.y + i][threadIdx.x] = src[(size_t)row * 1024 + k0 + threadIdx.x];
    }
    __syncthreads();
#pragma unroll
    for (int i = 0; i < 32; i += 8)
        dst[(size_t)(k0 + threadIdx.y + i) * 4096 + n0 + threadIdx.x] = t[threadIdx.x][threadIdx.y + i];
}

// ---------------- init + mask decode ----------------
__global__ void mask_init(const unsigned char* __restrict__ p,
                          const float* __restrict__ enc_b, const float* __restrict__ dec_b)
{
    int tid = threadIdx.x;
    int i = blockIdx.x * 512 + tid;
    g_c[i] = 0.0f;
    g_hB[0][i] = 0.0f;
    if (i < 4096) {
        int row = ((i & 3) << 10) + (i >> 2);
        g_bpe[i] = enc_b[row];
        g_bpd[i] = dec_b[row];
    }
    if (blockIdx.x == 2) {
#pragma unroll
        for (int k = 0; k < 8; ++k) g_flagG[tid + 512 * k] = 0u;
    }
    if (blockIdx.x == 3) {
#pragma unroll
        for (int k = 0; k < 8; ++k) g_flagC[tid + 512 * k] = 0u;
    }
    if (blockIdx.x == 0) {
        __shared__ int s_odd, s_big;
        if (tid == 0) { s_odd = 0; s_big = 0; }
        __syncthreads();
        unsigned char v = p[tid];
        if ((tid & 3) && v)  atomicOr(&s_odd, 1);
        if (v > 1)           atomicOr(&s_big, 1);
        __syncthreads();
        int m;
        if (s_big)        m = (((const float*)p)[tid] != 0.0f);
        else if (s_odd)   m = (p[tid] != 0);
        else              m = (((const int*)p)[tid] != 0);
        g_mask[tid] = m;
    }
}

// ---------------- host ----------------
extern "C" void kernel_launch(void* const* d_in, const int* in_sizes, int n_in,
                              void* d_out, int out_size)
{
    (void)in_sizes; (void)n_in; (void)out_size;
    const float* x       = (const float*)d_in[0];
    const float* target  = (const float*)d_in[1];
    const float* enc_Wih = (const float*)d_in[2];
    const float* enc_Whh = (const float*)d_in[3];
    const float* enc_b   = (const float*)d_in[4];
    const float* dec_Wih = (const float*)d_in[5];
    const float* dec_Whh = (const float*)d_in[6];
    const float* dec_b   = (const float*)d_in[7];
    const float* fc_W    = (const float*)d_in[8];
    const float* fc_b    = (const float*)d_in[9];
    const unsigned char* tf_mask = (const unsigned char*)d_in[10];
    float* out = (float*)d_out;

    static int smem_set = 0;
    if (!smem_set) {
        cudaFuncSetAttribute(seq2seq_persist,
                             cudaFuncAttributeMaxDynamicSharedMemorySize, SMEM_BYTES);
        smem_set = 1;
    }

    // #1: init + mask decode (+ flag reset)
    mask_init<<<128, 512>>>(tf_mask, enc_b, dec_b);
    // #2: weight transposes
    tposeAll<<<dim3(32, 128, 5), dim3(32, 8)>>>(enc_Wih, enc_Whh, dec_Wih, dec_Whh, fc_W);
    // #3: gatesX + tgtX + W0 + b_fused
    big_pre<<<dim3(32, 521), 256>>>(x, target, fc_b);
    // #4 (profiled): persistent recurrence
    seq2seq_persist<<<NBLK, 256, SMEM_BYTES>>>(x);
    // #5: all predictions post-hoc
    preds_out<<<dim3(8, 256), 256>>>(fc_b, out);
}